// round 10
// baseline (speedup 1.0000x reference)
#include <cuda_runtime.h>
#include <cuda_bf16.h>
#include <stdint.h>

#define BB 64
#define CC 3
#define JJ 11
#define TT 512
#define CO 128
#define NPTS (BB*JJ*TT)      /* 360448 = 2816*128 */
#define SIGC 84
#define K1A 168
#define K2A 256
#define NT 128
#define GRIDG (NPTS/NT)      /* 2816 */
#define RAWG (BB*JJ)
#define KS 32

// ---------------- static scratch ----------------
__device__ float g_S[(size_t)K1A * NPTS];    // sig, tf32-rounded fp32, [k][p]
__device__ float g_V[(size_t)CO * NPTS];     // ps output (V), [k][p]
__device__ float g_F[(size_t)CO * NPTS];     // fus pre-BN
__device__ uint4 g_Aps[6*1024];              // A fragment images per k32 chunk
__device__ uint4 g_Afus[8*1024];
__device__ float g_pU[RAWG*CO],   g_pUQ[RAWG*CO];
__device__ float g_pV[GRIDG*CO],  g_pVQ[GRIDG*CO];
__device__ float g_pF[GRIDG*CO],  g_pFQ[GRIDG*CO];
__device__ float g_sc1[K2A], g_bi1[K2A];
__device__ float g_sc2[CO],  g_bi2[CO];

// ---------------- PTX helpers ----------------
__device__ __forceinline__ uint32_t smem_u32(const void* p) {
    uint32_t a;
    asm("{ .reg .u64 t; cvta.to.shared.u64 t, %1; cvt.u32.u64 %0, t; }" : "=r"(a) : "l"(p));
    return a;
}
__device__ __forceinline__ uint32_t tf32r(float x) {
    uint32_t u;
    asm("cvt.rna.tf32.f32 %0, %1;" : "=r"(u) : "f"(x));
    return u;
}
__device__ __forceinline__ void mma_tf32(float (&d)[4], const uint4& a,
                                         uint32_t b0, uint32_t b1) {
    asm volatile("mma.sync.aligned.m16n8k8.row.col.f32.tf32.tf32.f32 "
        "{%0,%1,%2,%3}, {%4,%5,%6,%7}, {%8,%9}, {%0,%1,%2,%3};"
        : "+f"(d[0]), "+f"(d[1]), "+f"(d[2]), "+f"(d[3])
        : "r"(a.x), "r"(a.y), "r"(a.z), "r"(a.w), "r"(b0), "r"(b1));
}
__device__ __forceinline__ void cp16(uint32_t dst, const void* src, uint32_t sz) {
    asm volatile("cp.async.cg.shared.global [%0], [%1], 16, %2;"
        :: "r"(dst), "l"(src), "r"(sz));
}
#define CP_COMMIT() asm volatile("cp.async.commit_group;")
#define CP_WAIT1()  asm volatile("cp.async.wait_group 1;")

// SMEM layout (bytes):
#define OFF_A(s)   ((s)*16384)             /* A frag, 2 stages x 16KB */
#define OFF_B(s)   (32768 + (s)*17408)     /* B tf32, 2 x (32 rows x 544B) */
#define OFF_RAW(s) (67584 + (s)*16384)     /* raw fp32 (V chunks), 2 x 16KB */
#define OFF_SC 100352
#define OFF_BI 101376
#define OFF_W  102400                      /* raw conv weights 128x9 */
#define OFF_XS 107008                      /* x slice 3 x 132 */
#define XSP 132
#define SMEM_GEMM 108672

// ---------------- depth-3 signature Chen step (c = 4) ----------------
__device__ __forceinline__ void sig_step(float S1[4], float S2[16], float S3[64],
                                         const float d[4]) {
    float dd[16];
#pragma unroll
    for (int i = 0; i < 4; i++)
#pragma unroll
        for (int j = 0; j < 4; j++) dd[i*4+j] = d[i]*d[j];
    float a[4];
#pragma unroll
    for (int i = 0; i < 4; i++) a[i] = 0.5f*S1[i] + d[i]*(1.0f/6.0f);
#pragma unroll
    for (int i = 0; i < 4; i++)
#pragma unroll
        for (int j = 0; j < 4; j++)
#pragma unroll
            for (int k = 0; k < 4; k++)
                S3[i*16+j*4+k] += S2[i*4+j]*d[k] + a[i]*dd[j*4+k];
#pragma unroll
    for (int i = 0; i < 4; i++)
#pragma unroll
        for (int j = 0; j < 4; j++)
            S2[i*4+j] += S1[i]*d[j] + 0.5f*dd[i*4+j];
#pragma unroll
    for (int i = 0; i < 4; i++) S1[i] += d[i];
}

__device__ __forceinline__ void wr1(int row, int p, float v) {
    g_S[(size_t)row*NPTS + p] = __uint_as_float(tf32r(v));
}
__device__ __forceinline__ void sig_write(int rowbase, int p,
                                          const float S1[4], const float S2[16],
                                          const float S3[64]) {
#pragma unroll
    for (int i = 0; i < 4; i++)  wr1(rowbase + i, p, S1[i]);
#pragma unroll
    for (int i = 0; i < 16; i++) wr1(rowbase + 4 + i, p, S2[i]);
#pragma unroll
    for (int i = 0; i < 64; i++) wr1(rowbase + 20 + i, p, S3[i]);
}

// ---------------- K1: signatures ----------------
__global__ void k_sig(const float* __restrict__ x, const int* __restrict__ path) {
    int p = blockIdx.x * blockDim.x + threadIdx.x;
    if (p >= NPTS) return;
    int t  = p & (TT - 1);
    int bj = p >> 9;
    int j  = bj % JJ;
    int b  = bj / JJ;
    const float* xb = x + (size_t)b * CC * JJ * TT;

    float S1[4], S2[16], S3[64];
    float prev[3], cur[3], d[4];

#pragma unroll
    for (int i = 0; i < 4; i++)  S1[i] = 0.f;
#pragma unroll
    for (int i = 0; i < 16; i++) S2[i] = 0.f;
#pragma unroll
    for (int i = 0; i < 64; i++) S3[i] = 0.f;

    int j0 = path[j*3+0], j1 = path[j*3+1], j2 = path[j*3+2];
#pragma unroll
    for (int c = 0; c < 3; c++) prev[c] = xb[(c*JJ + j0)*TT + t];
    d[0] = 0.f; d[1] = prev[0]; d[2] = prev[1]; d[3] = prev[2];
    sig_step(S1, S2, S3, d);
#pragma unroll
    for (int c = 0; c < 3; c++) cur[c] = xb[(c*JJ + j1)*TT + t];
    d[0] = 0.5f;
#pragma unroll
    for (int c = 0; c < 3; c++) { d[c+1] = cur[c] - prev[c]; prev[c] = cur[c]; }
    sig_step(S1, S2, S3, d);
#pragma unroll
    for (int c = 0; c < 3; c++) cur[c] = xb[(c*JJ + j2)*TT + t];
    d[0] = 0.5f;
#pragma unroll
    for (int c = 0; c < 3; c++) d[c+1] = cur[c] - prev[c];
    sig_step(S1, S2, S3, d);
    sig_write(0, p, S1, S2, S3);

#pragma unroll
    for (int i = 0; i < 4; i++)  S1[i] = 0.f;
#pragma unroll
    for (int i = 0; i < 16; i++) S2[i] = 0.f;
#pragma unroll
    for (int i = 0; i < 64; i++) S3[i] = 0.f;

#pragma unroll
    for (int l = 0; l < 7; l++) {
        int tc = t + l - 3;
        tc = tc < 0 ? 0 : (tc > TT-1 ? TT-1 : tc);
#pragma unroll
        for (int c = 0; c < 3; c++) cur[c] = xb[(c*JJ + j)*TT + tc];
        if (l == 0) {
            d[0] = 0.f;
#pragma unroll
            for (int c = 0; c < 3; c++) d[c+1] = cur[c];
        } else {
            d[0] = 1.0f/6.0f;
#pragma unroll
            for (int c = 0; c < 3; c++) d[c+1] = cur[c] - prev[c];
        }
#pragma unroll
        for (int c = 0; c < 3; c++) prev[c] = cur[c];
        sig_step(S1, S2, S3, d);
    }
    sig_write(SIGC, p, S1, S2, S3);
}

// ---------------- K2: U statistics only (conv + reduce, NO store) ----------------
__global__ void k_ustat(const float* __restrict__ x, const float* __restrict__ w,
                        const float* __restrict__ b) {
    __shared__ float xs[3][TT + 2];
    __shared__ float ws[CO * 9];
    __shared__ float bs[CO];
    int bj = blockIdx.x;
    int j = bj % JJ, bb = bj / JJ;
    int tid = threadIdx.x;
    int warp = tid >> 5, lane = tid & 31;

    for (int i = tid; i < 3*(TT+2); i += 256) {
        int c = i / (TT+2), tt = i % (TT+2);
        xs[c][tt] = (tt >= 1 && tt <= TT) ? x[((bb*3 + c)*JJ + j)*TT + tt - 1] : 0.f;
    }
    for (int i = tid; i < CO*9; i += 256) ws[i] = w[i];
    if (tid < CO) bs[tid] = b[tid];
    __syncthreads();

#pragma unroll 1
    for (int oi = 0; oi < 16; oi++) {
        int o = warp*16 + oi;
        float wr[9];
#pragma unroll
        for (int i = 0; i < 9; i++) wr[i] = ws[o*9 + i];
        float bo = bs[o];
        float s = 0.f, q = 0.f;
#pragma unroll
        for (int i = 0; i < 16; i++) {
            int t = i*32 + lane;
            float a = bo;
#pragma unroll
            for (int c = 0; c < 3; c++)
#pragma unroll
                for (int kw = 0; kw < 3; kw++)
                    a = fmaf(xs[c][t + kw], wr[c*3 + kw], a);
            s += a; q += a*a;
        }
#pragma unroll
        for (int d = 16; d; d >>= 1) {
            s += __shfl_xor_sync(0xffffffffu, s, d);
            q += __shfl_xor_sync(0xffffffffu, q, d);
        }
        if (lane == 0) { g_pU[bj*CO + o] = s; g_pUQ[bj*CO + o] = q; }
    }
}

// ---------------- prep: A fragment images (tf32) ----------------
__global__ void k_prep(const float* __restrict__ psw, const float* __restrict__ fusw) {
    int which = blockIdx.x;
    const float* W = which ? fusw : psw;
    int K = which ? K2A : K1A;
    int nslot = which ? 8*1024 : 6*1024;
    uint4* A = which ? g_Afus : g_Aps;
    for (int s = threadIdx.x; s < nslot; s += blockDim.x) {
        int lane = s & 31, ks = (s >> 5) & 3, g = (s >> 7) & 7, kc = s >> 10;
        int r = g*16 + (lane >> 2);
        int kg = kc*32 + ks*8 + (lane & 3);
        float a0 = (kg < K)     ? W[r*K + kg]         : 0.f;
        float a1 = (kg < K)     ? W[(r+8)*K + kg]     : 0.f;
        float a2 = (kg+4 < K)   ? W[r*K + kg + 4]     : 0.f;
        float a3 = (kg+4 < K)   ? W[(r+8)*K + kg + 4] : 0.f;
        A[s] = make_uint4(tf32r(a0), tf32r(a1), tf32r(a2), tf32r(a3));
    }
}

// ---------------- GEMM building blocks ----------------
__device__ __forceinline__ void issueA(int c, int tid, uint32_t sb, const uint4* Aimg) {
#pragma unroll
    for (int i = 0; i < 4; i++) {
        int m = tid + i*256;
        cp16(sb + OFF_A(c & 1) + m*16, Aimg + c*1024 + m, 16);
    }
}
__device__ __forceinline__ void issueB0(int c, int tid, uint32_t sb, int p0) {
#pragma unroll
    for (int i = 0; i < 4; i++) {
        int m = tid + i*256;
        int kl = m >> 5, seg = m & 31;
        int kg = c*KS + kl;
        int ok = kg < K1A;
        const float* src = g_S + (size_t)(ok ? kg : 0)*NPTS + p0 + seg*4;
        cp16(sb + OFF_B(c & 1) + kl*544 + seg*16, src, ok ? 16u : 0u);
    }
}
// V rows for fus chunks 4..7
__device__ __forceinline__ void issueRawV(int c, int tid, uint32_t sb, int p0) {
#pragma unroll
    for (int i = 0; i < 4; i++) {
        int m = tid + i*256;
        int kl = m >> 5, seg = m & 31;
        const float* src = g_V + (size_t)((c-4)*KS + kl)*NPTS + p0 + seg*4;
        cp16(sb + OFF_RAW(c & 1) + m*16, src, 16);
    }
}
// affine+relu+tf32 on V chunk cc (4..7)
__device__ __forceinline__ void convV(int cc, int tid, char* smc,
        const float* s_sc, const float* s_bi) {
    const char* raw = smc + OFF_RAW(cc & 1);
    char* B = smc + OFF_B(cc & 1);
#pragma unroll
    for (int i = 0; i < 4; i++) {
        int m = tid + i*256;
        int kl = m >> 5, seg = m & 31;
        float4 v = *(const float4*)(raw + m*16);
        int kg = cc*KS + kl;
        float sc = s_sc[kg], bi = s_bi[kg];
        uint4 o;
        o.x = tf32r(fmaxf(fmaf(v.x, sc, bi), 0.f));
        o.y = tf32r(fmaxf(fmaf(v.y, sc, bi), 0.f));
        o.z = tf32r(fmaxf(fmaf(v.z, sc, bi), 0.f));
        o.w = tf32r(fmaxf(fmaf(v.w, sc, bi), 0.f));
        *(uint4*)(B + kl*544 + seg*16) = o;
    }
}
// inline U chunk cc (0..3): conv1x3 on xs + affine(+folded raw bias)+relu+tf32
__device__ __forceinline__ void convU(int cc, int tid, char* smc) {
    char* B = smc + OFF_B(cc & 1);
    const float* xs   = (const float*)(smc + OFF_XS);
    const float* ws   = (const float*)(smc + OFF_W);
    const float* s_sc = (const float*)(smc + OFF_SC);
    const float* s_bi = (const float*)(smc + OFF_BI);
    int ol = tid & 31;                 // lanes span channels -> x reads broadcast
    int o  = cc*KS + ol;
    int pseg = (tid >> 5) * 16;        // warp id -> 16-point segment
    float w[9];
#pragma unroll
    for (int i = 0; i < 9; i++) w[i] = ws[o*9 + i];
    float sc = s_sc[o], bi = s_bi[o];  // bi has raw bias folded for o<128
    const float* x0 = xs + pseg;
    const float* x1 = xs + XSP + pseg;
    const float* x2 = xs + 2*XSP + pseg;
    uint4 ob;
    uint32_t* obp = (uint32_t*)&ob;
#pragma unroll
    for (int i = 0; i < 16; i++) {
        float a =        x0[i]   * w[0];
        a = fmaf(x0[i+1], w[1], a);
        a = fmaf(x0[i+2], w[2], a);
        a = fmaf(x1[i],   w[3], a);
        a = fmaf(x1[i+1], w[4], a);
        a = fmaf(x1[i+2], w[5], a);
        a = fmaf(x2[i],   w[6], a);
        a = fmaf(x2[i+1], w[7], a);
        a = fmaf(x2[i+2], w[8], a);
        float v = fmaxf(fmaf(a, sc, bi), 0.f);
        obp[i & 3] = tf32r(v);
        if ((i & 3) == 3)
            *(uint4*)(B + ol*544 + (pseg + i - 3)*4) = ob;
    }
}

// ---------------- pipelined tf32 GEMM ----------------
__global__ void __launch_bounds__(256, 2) k_gemm_tc(int mode, const float* __restrict__ bias,
        const float* __restrict__ x, const float* __restrict__ rw,
        const float* __restrict__ rb) {
    extern __shared__ char smc[];
    __shared__ float sS[CO], sQ[CO];
    uint32_t sb = smem_u32(smc);
    float* s_sc = (float*)(smc + OFF_SC);
    float* s_bi = (float*)(smc + OFF_BI);

    int tid = threadIdx.x;
    int warp = tid >> 5, lane = tid & 31;
    int wm = (warp >> 2) * 64;
    int wn = (warp & 3) * 32;
    int gbase = (warp >> 2) * 4;
    int lq = lane >> 2, lr = lane & 3;
    // ps: reverse tile order (read k_sig output hot in L2); fus: ascending
    int p0 = mode ? blockIdx.x * NT : (GRIDG - 1 - (int)blockIdx.x) * NT;

    int kchunks = mode ? 8 : 6;
    const uint4* Aimg = mode ? g_Afus : g_Aps;
    float* Out = mode ? g_F : g_V;
    float* pS  = mode ? g_pF : g_pV;
    float* pQ  = mode ? g_pFQ : g_pVQ;

    if (mode) {
        for (int i = tid; i < K2A; i += 256) {
            float sc = g_sc1[i];
            s_sc[i] = sc;
            s_bi[i] = (i < CO) ? fmaf(sc, rb[i], g_bi1[i]) : g_bi1[i];
        }
        for (int i = tid; i < CO*9; i += 256) ((float*)(smc + OFF_W))[i] = rw[i];
        int bj = p0 >> 9, t0 = p0 & (TT-1);
        int b = bj / JJ, j = bj % JJ;
        for (int i = tid; i < 3*XSP; i += 256) {
            int c = i / XSP, ii = i % XSP;
            int t = t0 - 1 + ii;
            float v = 0.f;
            if (ii < 130 && t >= 0 && t < TT)
                v = x[((b*CC + c)*JJ + j)*TT + t];
            ((float*)(smc + OFF_XS))[i] = v;
        }
    }
    if (tid < CO) { sS[tid] = 0.f; sQ[tid] = 0.f; }
    __syncthreads();

    float acc[4][4][4];
#pragma unroll
    for (int i = 0; i < 4; i++)
#pragma unroll
        for (int j = 0; j < 4; j++)
#pragma unroll
            for (int r = 0; r < 4; r++) acc[i][j][r] = 0.f;

    // ---- prologue ----
    issueA(0, tid, sb, Aimg);
    if (!mode) issueB0(0, tid, sb, p0);
    CP_COMMIT();
    issueA(1, tid, sb, Aimg);
    if (!mode) issueB0(1, tid, sb, p0);
    CP_COMMIT();
    CP_WAIT1();
    if (mode) convU(0, tid, smc);
    __syncthreads();

    for (int c = 0; c < kchunks; c++) {
        int s = c & 1;
        const char* As = smc + OFF_A(s);
        const char* Bs = smc + OFF_B(s);
#pragma unroll
        for (int ks = 0; ks < 4; ks++) {
            uint4 af[4];
#pragma unroll
            for (int i = 0; i < 4; i++)
                af[i] = *(const uint4*)(As + ((gbase + i)*4 + ks)*512 + lane*16);
#pragma unroll
            for (int j = 0; j < 4; j++) {
                const char* bp = Bs + (ks*8 + lr)*544 + (wn + j*8 + lq)*4;
                uint32_t b0 = *(const uint32_t*)bp;
                uint32_t b1 = *(const uint32_t*)(bp + 4*544);
#pragma unroll
                for (int i = 0; i < 4; i++)
                    mma_tf32(acc[i][j], af[i], b0, b1);
            }
        }
        __syncthreads();
        if (c + 2 < kchunks) {
            issueA(c+2, tid, sb, Aimg);
            if (mode) { if (c + 2 >= 4) issueRawV(c+2, tid, sb, p0); }
            else issueB0(c+2, tid, sb, p0);
        }
        CP_COMMIT();
        CP_WAIT1();
        if (c + 1 < kchunks && mode) {
            if (c + 1 < 4) convU(c+1, tid, smc);
            else           convV(c+1, tid, smc, s_sc, s_bi);
        }
        __syncthreads();
    }

    // ---- epilogue ----
#pragma unroll
    for (int i = 0; i < 4; i++) {
        int c0 = wm + i*16 + lq;
        int c1 = c0 + 8;
        float b0 = bias[c0], b1 = bias[c1];
        float s0 = 0.f, q0 = 0.f, s1 = 0.f, q1 = 0.f;
#pragma unroll
        for (int j = 0; j < 4; j++) {
            float v00 = acc[i][j][0] + b0, v01 = acc[i][j][1] + b0;
            float v10 = acc[i][j][2] + b1, v11 = acc[i][j][3] + b1;
            int p = p0 + wn + j*8 + (lr << 1);
            *(float2*)&Out[(size_t)c0*NPTS + p] = make_float2(v00, v01);
            *(float2*)&Out[(size_t)c1*NPTS + p] = make_float2(v10, v11);
            s0 += v00 + v01; q0 += v00*v00 + v01*v01;
            s1 += v10 + v11; q1 += v10*v10 + v11*v11;
        }
#pragma unroll
        for (int d = 1; d < 4; d <<= 1) {
            s0 += __shfl_xor_sync(0xffffffffu, s0, d);
            q0 += __shfl_xor_sync(0xffffffffu, q0, d);
            s1 += __shfl_xor_sync(0xffffffffu, s1, d);
            q1 += __shfl_xor_sync(0xffffffffu, q1, d);
        }
        if (lr == 0) {
            atomicAdd(&sS[c0], s0); atomicAdd(&sQ[c0], q0);
            atomicAdd(&sS[c1], s1); atomicAdd(&sQ[c1], q1);
        }
    }
    __syncthreads();
    if (tid < CO) {
        pS[blockIdx.x*CO + tid] = sS[tid];
        pQ[blockIdx.x*CO + tid] = sQ[tid];
    }
}

// ---------------- finalize BN affines ----------------
__global__ void k_fin1(const float* __restrict__ rg, const float* __restrict__ rb,
                       const float* __restrict__ pg, const float* __restrict__ pb) {
    int c = blockIdx.x;   // 0..255
    float s = 0.f, q = 0.f;
    if (c < CO) {
        for (int i = threadIdx.x; i < RAWG; i += 128) { s += g_pU[i*CO + c]; q += g_pUQ[i*CO + c]; }
    } else {
        int cc = c - CO;
        for (int i = threadIdx.x; i < GRIDG; i += 128) { s += g_pV[i*CO + cc]; q += g_pVQ[i*CO + cc]; }
    }
    __shared__ float sh[256];
    sh[threadIdx.x] = s; sh[128 + threadIdx.x] = q;
    __syncthreads();
    for (int st = 64; st; st >>= 1) {
        if (threadIdx.x < st) {
            sh[threadIdx.x]       += sh[threadIdx.x + st];
            sh[128 + threadIdx.x] += sh[128 + threadIdx.x + st];
        }
        __syncthreads();
    }
    if (threadIdx.x == 0) {
        float mean = sh[0] / (float)NPTS;
        float var  = sh[128] / (float)NPTS - mean*mean;
        float rstd = rsqrtf(var + 1e-5f);
        float g  = (c < CO) ? rg[c] : pg[c - CO];
        float be = (c < CO) ? rb[c] : pb[c - CO];
        g_sc1[c] = rstd * g;
        g_bi1[c] = be - mean * rstd * g;
    }
}

__global__ void k_fin2(const float* __restrict__ fg, const float* __restrict__ fb) {
    int c = blockIdx.x;   // 0..127
    float s = 0.f, q = 0.f;
    for (int i = threadIdx.x; i < GRIDG; i += 128) { s += g_pF[i*CO + c]; q += g_pFQ[i*CO + c]; }
    __shared__ float sh[256];
    sh[threadIdx.x] = s; sh[128 + threadIdx.x] = q;
    __syncthreads();
    for (int st = 64; st; st >>= 1) {
        if (threadIdx.x < st) {
            sh[threadIdx.x]       += sh[threadIdx.x + st];
            sh[128 + threadIdx.x] += sh[128 + threadIdx.x + st];
        }
        __syncthreads();
    }
    if (threadIdx.x == 0) {
        float mean = sh[0] / (float)NPTS;
        float var  = sh[128] / (float)NPTS - mean*mean;
        float rstd = rsqrtf(var + 1e-5f);
        g_sc2[c] = rstd * fg[c];
        g_bi2[c] = fb[c] - mean * rstd * fg[c];
    }
}

// ---------------- final affine + relu + reshape (float4, reversed order) ----------------
__global__ void k_out(float* __restrict__ out) {
    int blk = gridDim.x - 1 - blockIdx.x;     // reversed: read fresh F tail first
    int e4 = blk * 256 + threadIdx.x;
    int idx = e4 << 2;
    int o = idx / NPTS;
    int p = idx - o * NPTS;
    int t  = p & (TT - 1);
    int bj = p >> 9;
    int j  = bj % JJ;
    int b  = bj / JJ;
    float4 v = *(const float4*)&g_F[idx];
    float sc = g_sc2[o], bi = g_bi2[o];
    v.x = fmaxf(fmaf(v.x, sc, bi), 0.f);
    v.y = fmaxf(fmaf(v.y, sc, bi), 0.f);
    v.z = fmaxf(fmaf(v.z, sc, bi), 0.f);
    v.w = fmaxf(fmaf(v.w, sc, bi), 0.f);
    *(float4*)&out[((b*CO + o)*JJ + j)*TT + t] = v;
}

// ---------------- launcher ----------------
extern "C" void kernel_launch(void* const* d_in, const int* in_sizes, int n_in,
                              void* d_out, int out_size) {
    const float* x      = (const float*)d_in[0];
    const int*   path   = (const int*)  d_in[1];
    const float* raw_w  = (const float*)d_in[2];
    const float* raw_b  = (const float*)d_in[3];
    const float* raw_g  = (const float*)d_in[4];
    const float* raw_be = (const float*)d_in[5];
    const float* ps_w   = (const float*)d_in[6];
    const float* ps_b   = (const float*)d_in[7];
    const float* ps_g   = (const float*)d_in[8];
    const float* ps_be  = (const float*)d_in[9];
    const float* fus_w  = (const float*)d_in[10];
    const float* fus_b  = (const float*)d_in[11];
    const float* fus_g  = (const float*)d_in[12];
    const float* fus_be = (const float*)d_in[13];
    float* out = (float*)d_out;

    cudaFuncSetAttribute(k_gemm_tc, cudaFuncAttributeMaxDynamicSharedMemorySize, SMEM_GEMM);

    k_prep<<<2, 256>>>(ps_w, fus_w);
    k_ustat<<<RAWG, 256>>>(x, raw_w, raw_b);
    k_sig<<<NPTS/256, 256>>>(x, path);
    k_gemm_tc<<<GRIDG, 256, SMEM_GEMM>>>(0, ps_b, x, raw_w, raw_b);
    k_fin1<<<2*CO, 128>>>(raw_g, raw_be, ps_g, ps_be);
    k_gemm_tc<<<GRIDG, 256, SMEM_GEMM>>>(1, fus_b, x, raw_w, raw_b);
    k_fin2<<<CO, 128>>>(fus_g, fus_be);
    k_out<<<(CO*NPTS)/1024, 256>>>(out);
}

// round 12
// speedup vs baseline: 1.3834x; 1.3834x over previous
#include <cuda_runtime.h>
#include <cuda_fp16.h>
#include <stdint.h>

#define BB 64
#define CC 3
#define JJ 11
#define TT 512
#define CO 128
#define NPTS (BB*JJ*TT)      /* 360448 = 2816*128 */
#define SIGC 84
#define K1A 168
#define K2A 256
#define NT 128
#define GRIDG (NPTS/NT)      /* 2816 */
#define RAWG (BB*JJ)
#define KS 32

// ---------------- static scratch ----------------
__device__ __half g_Sh[(size_t)K1A * NPTS];   // sig fp16, [k][p]
__device__ __half g_UVh[(size_t)K2A * NPTS];  // rows 0..127 = U, 128..255 = V (fp16)
__device__ __half g_Fh[(size_t)CO * NPTS];    // fus pre-BN (fp16)
__device__ uint4 g_Aps[6*512];                // fp16 A frag images per k32 chunk
__device__ uint4 g_Afus[8*512];
__device__ float g_pU[RAWG*CO],   g_pUQ[RAWG*CO];
__device__ float g_pV[GRIDG*CO],  g_pVQ[GRIDG*CO];
__device__ float g_pF[GRIDG*CO],  g_pFQ[GRIDG*CO];
__device__ float g_sc1[K2A], g_bi1[K2A];
__device__ float g_sc2[CO],  g_bi2[CO];

// ---------------- PTX helpers ----------------
__device__ __forceinline__ uint32_t smem_u32(const void* p) {
    uint32_t a;
    asm("{ .reg .u64 t; cvta.to.shared.u64 t, %1; cvt.u32.u64 %0, t; }" : "=r"(a) : "l"(p));
    return a;
}
__device__ __forceinline__ void ldsm_x2_t(uint32_t (&r)[2], uint32_t addr) {
    asm volatile("ldmatrix.sync.aligned.m8n8.x2.trans.shared.b16 {%0,%1}, [%2];"
        : "=r"(r[0]), "=r"(r[1]) : "r"(addr));
}
__device__ __forceinline__ void mma_f16(float (&d)[4], const uint4& a,
                                        uint32_t b0, uint32_t b1) {
    asm volatile("mma.sync.aligned.m16n8k16.row.col.f32.f16.f16.f32 "
        "{%0,%1,%2,%3}, {%4,%5,%6,%7}, {%8,%9}, {%0,%1,%2,%3};"
        : "+f"(d[0]), "+f"(d[1]), "+f"(d[2]), "+f"(d[3])
        : "r"(a.x), "r"(a.y), "r"(a.z), "r"(a.w), "r"(b0), "r"(b1));
}
__device__ __forceinline__ void cp16(uint32_t dst, const void* src, uint32_t sz) {
    asm volatile("cp.async.cg.shared.global [%0], [%1], 16, %2;"
        :: "r"(dst), "l"(src), "r"(sz));
}
#define CP_COMMIT() asm volatile("cp.async.commit_group;")
#define CP_WAIT1()  asm volatile("cp.async.wait_group 1;")

__device__ __forceinline__ uint32_t packh2(float a, float b) {
    __half2 h = __floats2half2_rn(a, b);
    return *(uint32_t*)&h;
}

// SMEM layout (bytes):
#define OFF_A(s)   ((s)*8192)              /* A frag fp16, 2 stages x 8KB */
#define OFF_B(s)   (16384 + (s)*8704)      /* B fp16, 2 x (32 rows x 272B) */
#define OFF_RAW(s) (33792 + (s)*8192)      /* raw fp16 (fus), 2 x (32 x 256B) */
#define OFF_SC 50176
#define OFF_BI 51200
#define SMEM_GEMM 52224

// ---------------- depth-3 signature Chen step (c = 4) ----------------
__device__ __forceinline__ void sig_step(float S1[4], float S2[16], float S3[64],
                                         const float d[4]) {
    float dd[16];
#pragma unroll
    for (int i = 0; i < 4; i++)
#pragma unroll
        for (int j = 0; j < 4; j++) dd[i*4+j] = d[i]*d[j];
    float a[4];
#pragma unroll
    for (int i = 0; i < 4; i++) a[i] = 0.5f*S1[i] + d[i]*(1.0f/6.0f);
#pragma unroll
    for (int i = 0; i < 4; i++)
#pragma unroll
        for (int j = 0; j < 4; j++)
#pragma unroll
            for (int k = 0; k < 4; k++)
                S3[i*16+j*4+k] += S2[i*4+j]*d[k] + a[i]*dd[j*4+k];
#pragma unroll
    for (int i = 0; i < 4; i++)
#pragma unroll
        for (int j = 0; j < 4; j++)
            S2[i*4+j] += S1[i]*d[j] + 0.5f*dd[i*4+j];
#pragma unroll
    for (int i = 0; i < 4; i++) S1[i] += d[i];
}

__device__ __forceinline__ void wr1(int row, int p, float v) {
    g_Sh[(size_t)row*NPTS + p] = __float2half_rn(v);
}
__device__ __forceinline__ void sig_write(int rowbase, int p,
                                          const float S1[4], const float S2[16],
                                          const float S3[64]) {
#pragma unroll
    for (int i = 0; i < 4; i++)  wr1(rowbase + i, p, S1[i]);
#pragma unroll
    for (int i = 0; i < 16; i++) wr1(rowbase + 4 + i, p, S2[i]);
#pragma unroll
    for (int i = 0; i < 64; i++) wr1(rowbase + 20 + i, p, S3[i]);
}

// ---------------- K1: signatures ----------------
__global__ void k_sig(const float* __restrict__ x, const int* __restrict__ path) {
    int p = blockIdx.x * blockDim.x + threadIdx.x;
    if (p >= NPTS) return;
    int t  = p & (TT - 1);
    int bj = p >> 9;
    int j  = bj % JJ;
    int b  = bj / JJ;
    const float* xb = x + (size_t)b * CC * JJ * TT;

    float S1[4], S2[16], S3[64];
    float prev[3], cur[3], d[4];

#pragma unroll
    for (int i = 0; i < 4; i++)  S1[i] = 0.f;
#pragma unroll
    for (int i = 0; i < 16; i++) S2[i] = 0.f;
#pragma unroll
    for (int i = 0; i < 64; i++) S3[i] = 0.f;

    int j0 = path[j*3+0], j1 = path[j*3+1], j2 = path[j*3+2];
#pragma unroll
    for (int c = 0; c < 3; c++) prev[c] = xb[(c*JJ + j0)*TT + t];
    d[0] = 0.f; d[1] = prev[0]; d[2] = prev[1]; d[3] = prev[2];
    sig_step(S1, S2, S3, d);
#pragma unroll
    for (int c = 0; c < 3; c++) cur[c] = xb[(c*JJ + j1)*TT + t];
    d[0] = 0.5f;
#pragma unroll
    for (int c = 0; c < 3; c++) { d[c+1] = cur[c] - prev[c]; prev[c] = cur[c]; }
    sig_step(S1, S2, S3, d);
#pragma unroll
    for (int c = 0; c < 3; c++) cur[c] = xb[(c*JJ + j2)*TT + t];
    d[0] = 0.5f;
#pragma unroll
    for (int c = 0; c < 3; c++) d[c+1] = cur[c] - prev[c];
    sig_step(S1, S2, S3, d);
    sig_write(0, p, S1, S2, S3);

#pragma unroll
    for (int i = 0; i < 4; i++)  S1[i] = 0.f;
#pragma unroll
    for (int i = 0; i < 16; i++) S2[i] = 0.f;
#pragma unroll
    for (int i = 0; i < 64; i++) S3[i] = 0.f;

#pragma unroll
    for (int l = 0; l < 7; l++) {
        int tc = t + l - 3;
        tc = tc < 0 ? 0 : (tc > TT-1 ? TT-1 : tc);
#pragma unroll
        for (int c = 0; c < 3; c++) cur[c] = xb[(c*JJ + j)*TT + tc];
        if (l == 0) {
            d[0] = 0.f;
#pragma unroll
            for (int c = 0; c < 3; c++) d[c+1] = cur[c];
        } else {
            d[0] = 1.0f/6.0f;
#pragma unroll
            for (int c = 0; c < 3; c++) d[c+1] = cur[c] - prev[c];
        }
#pragma unroll
        for (int c = 0; c < 3; c++) prev[c] = cur[c];
        sig_step(S1, S2, S3, d);
    }
    sig_write(SIGC, p, S1, S2, S3);
}

// ---------------- K2: raw conv + bias -> U fp16 + fused BN partials ----------------
__global__ void k_raw(const float* __restrict__ x, const float* __restrict__ w,
                      const float* __restrict__ b) {
    __shared__ float xs[3][TT + 2];
    __shared__ float ws[CO * 9];
    __shared__ float bs[CO];
    int bj = blockIdx.x;
    int j = bj % JJ, bb = bj / JJ;
    int tid = threadIdx.x;
    int warp = tid >> 5, lane = tid & 31;

    for (int i = tid; i < 3*(TT+2); i += 256) {
        int c = i / (TT+2), tt = i % (TT+2);
        xs[c][tt] = (tt >= 1 && tt <= TT) ? x[((bb*3 + c)*JJ + j)*TT + tt - 1] : 0.f;
    }
    for (int i = tid; i < CO*9; i += 256) ws[i] = w[i];
    if (tid < CO) bs[tid] = b[tid];
    __syncthreads();

    int pbase = bj * TT;
#pragma unroll 1
    for (int oi = 0; oi < 16; oi++) {
        int o = warp*16 + oi;
        float wr[9];
#pragma unroll
        for (int i = 0; i < 9; i++) wr[i] = ws[o*9 + i];
        float bo = bs[o];
        float s = 0.f, q = 0.f;
        __half* orow = g_UVh + (size_t)o*NPTS + pbase;
#pragma unroll
        for (int i = 0; i < 16; i++) {
            int t = i*32 + lane;
            float a = bo;
#pragma unroll
            for (int c = 0; c < 3; c++)
#pragma unroll
                for (int kw = 0; kw < 3; kw++)
                    a = fmaf(xs[c][t + kw], wr[c*3 + kw], a);
            orow[t] = __float2half_rn(a);
            s += a; q += a*a;
        }
#pragma unroll
        for (int d = 16; d; d >>= 1) {
            s += __shfl_xor_sync(0xffffffffu, s, d);
            q += __shfl_xor_sync(0xffffffffu, q, d);
        }
        if (lane == 0) { g_pU[bj*CO + o] = s; g_pUQ[bj*CO + o] = q; }
    }
}

// ---------------- prep: fp16 A fragment images (m16n8k16 layout) ----------------
__global__ void k_prep(const float* __restrict__ psw, const float* __restrict__ fusw) {
    int which = blockIdx.x;
    const float* W = which ? fusw : psw;
    int K = which ? K2A : K1A;
    int nslot = which ? 8*512 : 6*512;
    uint4* A = which ? g_Afus : g_Aps;
    for (int s = threadIdx.x; s < nslot; s += blockDim.x) {
        int lane = s & 31, ks = (s >> 5) & 1, g = (s >> 6) & 7, kc = s >> 9;
        int r = g*16 + (lane >> 2);
        int kb = kc*32 + ks*16 + 2*(lane & 3);
        float a00 = (kb   < K) ? W[r*K + kb]       : 0.f;
        float a01 = (kb+1 < K) ? W[r*K + kb+1]     : 0.f;
        float a10 = (kb   < K) ? W[(r+8)*K + kb]   : 0.f;
        float a11 = (kb+1 < K) ? W[(r+8)*K + kb+1] : 0.f;
        float a20 = (kb+8 < K) ? W[r*K + kb+8]     : 0.f;
        float a21 = (kb+9 < K) ? W[r*K + kb+9]     : 0.f;
        float a30 = (kb+8 < K) ? W[(r+8)*K + kb+8] : 0.f;
        float a31 = (kb+9 < K) ? W[(r+8)*K + kb+9] : 0.f;
        A[s] = make_uint4(packh2(a00, a01), packh2(a10, a11),
                          packh2(a20, a21), packh2(a30, a31));
    }
}

// ---------------- GEMM building blocks ----------------
__device__ __forceinline__ void issueA(int c, int tid, uint32_t sb, const uint4* Aimg) {
#pragma unroll
    for (int i = 0; i < 2; i++) {
        int m = tid + i*256;
        cp16(sb + OFF_A(c & 1) + m*16, Aimg + c*512 + m, 16);
    }
}
__device__ __forceinline__ void issueB0(int c, int tid, uint32_t sb, int p0) {
#pragma unroll
    for (int i = 0; i < 2; i++) {
        int m = tid + i*256;
        int kl = m >> 4, seg = m & 15;
        int kg = c*KS + kl;
        int ok = kg < K1A;
        const __half* src = g_Sh + (size_t)(ok ? kg : 0)*NPTS + p0 + seg*8;
        cp16(sb + OFF_B(c & 1) + kl*272 + seg*16, src, ok ? 16u : 0u);
    }
}
__device__ __forceinline__ void issueRaw(int c, int tid, uint32_t sb, int p0) {
#pragma unroll
    for (int i = 0; i < 2; i++) {
        int m = tid + i*256;
        int kl = m >> 4, seg = m & 15;
        const __half* src = g_UVh + (size_t)(c*KS + kl)*NPTS + p0 + seg*8;
        cp16(sb + OFF_RAW(c & 1) + m*16, src, 16);
    }
}
// affine+relu on fus chunk cc: raw[cc&1] (fp16) -> B[cc&1] (fp16)
__device__ __forceinline__ void convF(int cc, int tid, char* smc,
        const float* s_sc, const float* s_bi) {
    const char* raw = smc + OFF_RAW(cc & 1);
    char* B = smc + OFF_B(cc & 1);
#pragma unroll
    for (int i = 0; i < 2; i++) {
        int m = tid + i*256;
        int kl = m >> 4, seg = m & 15;
        uint4 v = *(const uint4*)(raw + m*16);
        int kg = cc*KS + kl;
        float sc = s_sc[kg], bi = s_bi[kg];
        uint4 o;
        uint32_t* vp = (uint32_t*)&v;
        uint32_t* op = (uint32_t*)&o;
#pragma unroll
        for (int q = 0; q < 4; q++) {
            float2 f = __half22float2(*(__half2*)&vp[q]);
            f.x = fmaxf(fmaf(f.x, sc, bi), 0.f);
            f.y = fmaxf(fmaf(f.y, sc, bi), 0.f);
            op[q] = packh2(f.x, f.y);
        }
        *(uint4*)(B + kl*272 + seg*16) = o;
    }
}

// ---------------- pipelined fp16 GEMM: D[128ch][128pts]/CTA, 256 thr, 2 CTA/SM ----------------
__global__ void __launch_bounds__(256, 2) k_gemm_tc(int mode, const float* __restrict__ bias) {
    extern __shared__ char smc[];
    __shared__ float sS[CO], sQ[CO];
    uint32_t sb = smem_u32(smc);
    float* s_sc = (float*)(smc + OFF_SC);
    float* s_bi = (float*)(smc + OFF_BI);

    int tid = threadIdx.x;
    int warp = tid >> 5, lane = tid & 31;
    int wm = (warp >> 2) * 64;
    int wn = (warp & 3) * 32;
    int gbase = (warp >> 2) * 4;
    int lq = lane >> 2, lr = lane & 3;
    int p0 = blockIdx.x * NT;

    int kchunks = mode ? 8 : 6;
    const uint4* Aimg = mode ? g_Afus : g_Aps;
    __half* Out = mode ? g_Fh : (g_UVh + (size_t)CO*NPTS);
    float* pS  = mode ? g_pF : g_pV;
    float* pQ  = mode ? g_pFQ : g_pVQ;

    if (mode)
        for (int i = tid; i < K2A; i += 256) { s_sc[i] = g_sc1[i]; s_bi[i] = g_bi1[i]; }
    if (tid < CO) { sS[tid] = 0.f; sQ[tid] = 0.f; }
    __syncthreads();

    float acc[4][4][4];
#pragma unroll
    for (int i = 0; i < 4; i++)
#pragma unroll
        for (int j = 0; j < 4; j++)
#pragma unroll
            for (int r = 0; r < 4; r++) acc[i][j][r] = 0.f;

    // ---- prologue ----
    issueA(0, tid, sb, Aimg);
    if (mode) issueRaw(0, tid, sb, p0); else issueB0(0, tid, sb, p0);
    CP_COMMIT();
    issueA(1, tid, sb, Aimg);
    if (mode) issueRaw(1, tid, sb, p0); else issueB0(1, tid, sb, p0);
    CP_COMMIT();
    CP_WAIT1();
    if (mode) convF(0, tid, smc, s_sc, s_bi);
    __syncthreads();

    for (int c = 0; c < kchunks; c++) {
        int s = c & 1;
        const char* As = smc + OFF_A(s);
#pragma unroll
        for (int ks = 0; ks < 2; ks++) {
            uint4 af[4];
#pragma unroll
            for (int i = 0; i < 4; i++)
                af[i] = *(const uint4*)(As + ((gbase + i)*2 + ks)*512 + lane*16);
#pragma unroll
            for (int j = 0; j < 4; j++) {
                uint32_t b[2];
                uint32_t boff = (uint32_t)((ks*16 + (lane & 15))*272 + (wn + j*8)*2);
                ldsm_x2_t(b, sb + OFF_B(s) + boff);
#pragma unroll
                for (int i = 0; i < 4; i++)
                    mma_f16(acc[i][j], af[i], b[0], b[1]);
            }
        }
        __syncthreads();
        if (c + 2 < kchunks) {
            issueA(c+2, tid, sb, Aimg);
            if (mode) issueRaw(c+2, tid, sb, p0); else issueB0(c+2, tid, sb, p0);
        }
        CP_COMMIT();
        CP_WAIT1();
        if (mode && c + 1 < kchunks) convF(c+1, tid, smc, s_sc, s_bi);
        __syncthreads();
    }

    // ---- epilogue: bias, store fp16 channel-major, fused BN partials ----
#pragma unroll
    for (int i = 0; i < 4; i++) {
        int c0 = wm + i*16 + lq;
        int c1 = c0 + 8;
        float b0 = bias[c0], b1 = bias[c1];
        float s0 = 0.f, q0 = 0.f, s1 = 0.f, q1 = 0.f;
#pragma unroll
        for (int j = 0; j < 4; j++) {
            float v00 = acc[i][j][0] + b0, v01 = acc[i][j][1] + b0;
            float v10 = acc[i][j][2] + b1, v11 = acc[i][j][3] + b1;
            int p = p0 + wn + j*8 + (lr << 1);
            __half2 h0 = __floats2half2_rn(v00, v01);
            __half2 h1 = __floats2half2_rn(v10, v11);
            *(__half2*)&Out[(size_t)c0*NPTS + p] = h0;
            *(__half2*)&Out[(size_t)c1*NPTS + p] = h1;
            s0 += v00 + v01; q0 += v00*v00 + v01*v01;
            s1 += v10 + v11; q1 += v10*v10 + v11*v11;
        }
#pragma unroll
        for (int d = 1; d < 4; d <<= 1) {
            s0 += __shfl_xor_sync(0xffffffffu, s0, d);
            q0 += __shfl_xor_sync(0xffffffffu, q0, d);
            s1 += __shfl_xor_sync(0xffffffffu, s1, d);
            q1 += __shfl_xor_sync(0xffffffffu, q1, d);
        }
        if (lr == 0) {
            atomicAdd(&sS[c0], s0); atomicAdd(&sQ[c0], q0);
            atomicAdd(&sS[c1], s1); atomicAdd(&sQ[c1], q1);
        }
    }
    __syncthreads();
    if (tid < CO) {
        pS[blockIdx.x*CO + tid] = sS[tid];
        pQ[blockIdx.x*CO + tid] = sQ[tid];
    }
}

// ---------------- finalize BN affines ----------------
__global__ void k_fin1(const float* __restrict__ rg, const float* __restrict__ rb,
                       const float* __restrict__ pg, const float* __restrict__ pb) {
    int c = blockIdx.x;   // 0..255
    float s = 0.f, q = 0.f;
    if (c < CO) {
        for (int i = threadIdx.x; i < RAWG; i += 128) { s += g_pU[i*CO + c]; q += g_pUQ[i*CO + c]; }
    } else {
        int cc = c - CO;
        for (int i = threadIdx.x; i < GRIDG; i += 128) { s += g_pV[i*CO + cc]; q += g_pVQ[i*CO + cc]; }
    }
    __shared__ float sh[256];
    sh[threadIdx.x] = s; sh[128 + threadIdx.x] = q;
    __syncthreads();
    for (int st = 64; st; st >>= 1) {
        if (threadIdx.x < st) {
            sh[threadIdx.x]       += sh[threadIdx.x + st];
            sh[128 + threadIdx.x] += sh[128 + threadIdx.x + st];
        }
        __syncthreads();
    }
    if (threadIdx.x == 0) {
        float mean = sh[0] / (float)NPTS;
        float var  = sh[128] / (float)NPTS - mean*mean;
        float rstd = rsqrtf(var + 1e-5f);
        float g  = (c < CO) ? rg[c] : pg[c - CO];
        float be = (c < CO) ? rb[c] : pb[c - CO];
        g_sc1[c] = rstd * g;
        g_bi1[c] = be - mean * rstd * g;
    }
}

__global__ void k_fin2(const float* __restrict__ fg, const float* __restrict__ fb) {
    int c = blockIdx.x;   // 0..127
    float s = 0.f, q = 0.f;
    for (int i = threadIdx.x; i < GRIDG; i += 128) { s += g_pF[i*CO + c]; q += g_pFQ[i*CO + c]; }
    __shared__ float sh[256];
    sh[threadIdx.x] = s; sh[128 + threadIdx.x] = q;
    __syncthreads();
    for (int st = 64; st; st >>= 1) {
        if (threadIdx.x < st) {
            sh[threadIdx.x]       += sh[threadIdx.x + st];
            sh[128 + threadIdx.x] += sh[128 + threadIdx.x + st];
        }
        __syncthreads();
    }
    if (threadIdx.x == 0) {
        float mean = sh[0] / (float)NPTS;
        float var  = sh[128] / (float)NPTS - mean*mean;
        float rstd = rsqrtf(var + 1e-5f);
        g_sc2[c] = rstd * fg[c];
        g_bi2[c] = fb[c] - mean * rstd * fg[c];
    }
}

// ---------------- final affine + relu + reshape (8 fp16 per thread) ----------------
__global__ void k_out(float* __restrict__ out) {
    int e8 = blockIdx.x * 256 + threadIdx.x;
    int idx = e8 << 3;
    int o = idx / NPTS;
    int p = idx - o * NPTS;
    int t  = p & (TT - 1);
    int bj = p >> 9;
    int j  = bj % JJ;
    int b  = bj / JJ;
    uint4 v = *(const uint4*)&g_Fh[idx];
    float sc = g_sc2[o], bi = g_bi2[o];
    const uint32_t* vp = (const uint32_t*)&v;
    float r[8];
#pragma unroll
    for (int q = 0; q < 4; q++) {
        float2 f = __half22float2(*(const __half2*)&vp[q]);
        r[q*2+0] = fmaxf(fmaf(f.x, sc, bi), 0.f);
        r[q*2+1] = fmaxf(fmaf(f.y, sc, bi), 0.f);
    }
    float* dst = &out[((b*CO + o)*JJ + j)*TT + t];
    *(float4*)dst       = make_float4(r[0], r[1], r[2], r[3]);
    *(float4*)(dst + 4) = make_float4(r[4], r[5], r[6], r[7]);
}

// ---------------- launcher ----------------
extern "C" void kernel_launch(void* const* d_in, const int* in_sizes, int n_in,
                              void* d_out, int out_size) {
    const float* x      = (const float*)d_in[0];
    const int*   path   = (const int*)  d_in[1];
    const float* raw_w  = (const float*)d_in[2];
    const float* raw_b  = (const float*)d_in[3];
    const float* raw_g  = (const float*)d_in[4];
    const float* raw_be = (const float*)d_in[5];
    const float* ps_w   = (const float*)d_in[6];
    const float* ps_b   = (const float*)d_in[7];
    const float* ps_g   = (const float*)d_in[8];
    const float* ps_be  = (const float*)d_in[9];
    const float* fus_w  = (const float*)d_in[10];
    const float* fus_b  = (const float*)d_in[11];
    const float* fus_g  = (const float*)d_in[12];
    const float* fus_be = (const float*)d_in[13];
    float* out = (float*)d_out;

    cudaFuncSetAttribute(k_gemm_tc, cudaFuncAttributeMaxDynamicSharedMemorySize, SMEM_GEMM);

    k_prep<<<2, 256>>>(ps_w, fus_w);
    k_sig<<<NPTS/256, 256>>>(x, path);
    k_raw<<<RAWG, 256>>>(x, raw_w, raw_b);
    k_gemm_tc<<<GRIDG, 256, SMEM_GEMM>>>(0, ps_b);
    k_fin1<<<2*CO, 128>>>(raw_g, raw_be, ps_g, ps_be);
    k_gemm_tc<<<GRIDG, 256, SMEM_GEMM>>>(1, fus_b);
    k_fin2<<<CO, 128>>>(fus_g, fus_be);
    k_out<<<(CO*NPTS)/2048, 256>>>(out);
}

// round 13
// speedup vs baseline: 1.4229x; 1.0286x over previous
#include <cuda_runtime.h>
#include <cuda_fp16.h>
#include <stdint.h>

#define BB 64
#define CC 3
#define JJ 11
#define TT 512
#define CO 128
#define NPTS (BB*JJ*TT)      /* 360448 = 2816*128 */
#define SIGC 84
#define K1A 168
#define K2A 256
#define NT 128
#define GRIDG (NPTS/NT)      /* 2816 */
#define RAWG (BB*JJ)
#define KS 64                /* GEMM k-chunk */

// ---------------- static scratch ----------------
__device__ __half g_Sh[(size_t)K1A * NPTS];   // sig fp16, [k][p]
__device__ __half g_UVh[(size_t)K2A * NPTS];  // rows 0..127 = U, 128..255 = V (fp16)
__device__ __half g_Fh[(size_t)CO * NPTS];    // fus pre-BN (fp16)
__device__ uint4 g_Aps[6*512];                // fp16 A frag images ([kc32] x 512 slots)
__device__ uint4 g_Afus[8*512];
__device__ float g_pU[RAWG*CO],   g_pUQ[RAWG*CO];
__device__ float g_pV[GRIDG*CO],  g_pVQ[GRIDG*CO];
__device__ float g_pF[GRIDG*CO],  g_pFQ[GRIDG*CO];
__device__ float g_sc1[K2A], g_bi1[K2A];
__device__ float g_sc2[CO],  g_bi2[CO];

// ---------------- PTX helpers ----------------
__device__ __forceinline__ uint32_t smem_u32(const void* p) {
    uint32_t a;
    asm("{ .reg .u64 t; cvta.to.shared.u64 t, %1; cvt.u32.u64 %0, t; }" : "=r"(a) : "l"(p));
    return a;
}
__device__ __forceinline__ void ldsm_x2_t(uint32_t (&r)[2], uint32_t addr) {
    asm volatile("ldmatrix.sync.aligned.m8n8.x2.trans.shared.b16 {%0,%1}, [%2];"
        : "=r"(r[0]), "=r"(r[1]) : "r"(addr));
}
__device__ __forceinline__ void mma_f16(float (&d)[4], const uint4& a,
                                        uint32_t b0, uint32_t b1) {
    asm volatile("mma.sync.aligned.m16n8k16.row.col.f32.f16.f16.f32 "
        "{%0,%1,%2,%3}, {%4,%5,%6,%7}, {%8,%9}, {%0,%1,%2,%3};"
        : "+f"(d[0]), "+f"(d[1]), "+f"(d[2]), "+f"(d[3])
        : "r"(a.x), "r"(a.y), "r"(a.z), "r"(a.w), "r"(b0), "r"(b1));
}
__device__ __forceinline__ void cp16(uint32_t dst, const void* src, uint32_t sz) {
    asm volatile("cp.async.cg.shared.global [%0], [%1], 16, %2;"
        :: "r"(dst), "l"(src), "r"(sz));
}
#define CP_COMMIT() asm volatile("cp.async.commit_group;")
#define CP_WAIT1()  asm volatile("cp.async.wait_group 1;")

__device__ __forceinline__ uint32_t packh2(float a, float b) {
    __half2 h = __floats2half2_rn(a, b);
    return *(uint32_t*)&h;
}

// SMEM layout (bytes):
#define OFF_A(s)   ((s)*16384)             /* A frag fp16, 2 stages x 16KB (2 kc32 imgs) */
#define OFF_B(s)   (32768 + (s)*17408)     /* B fp16, 2 x (64 rows x 272B) */
#define OFF_RAW(s) (67584 + (s)*16384)     /* raw fp16 (fus), 2 x (64 x 256B) */
#define OFF_SC 100352
#define OFF_BI 101376
#define SMEM_GEMM 102400

// ---------------- depth-3 signature Chen step (c = 4) ----------------
__device__ __forceinline__ void sig_step(float S1[4], float S2[16], float S3[64],
                                         const float d[4]) {
    float dd[16];
#pragma unroll
    for (int i = 0; i < 4; i++)
#pragma unroll
        for (int j = 0; j < 4; j++) dd[i*4+j] = d[i]*d[j];
    float a[4];
#pragma unroll
    for (int i = 0; i < 4; i++) a[i] = 0.5f*S1[i] + d[i]*(1.0f/6.0f);
#pragma unroll
    for (int i = 0; i < 4; i++)
#pragma unroll
        for (int j = 0; j < 4; j++)
#pragma unroll
            for (int k = 0; k < 4; k++)
                S3[i*16+j*4+k] += S2[i*4+j]*d[k] + a[i]*dd[j*4+k];
#pragma unroll
    for (int i = 0; i < 4; i++)
#pragma unroll
        for (int j = 0; j < 4; j++)
            S2[i*4+j] += S1[i]*d[j] + 0.5f*dd[i*4+j];
#pragma unroll
    for (int i = 0; i < 4; i++) S1[i] += d[i];
}

__device__ __forceinline__ void wr1(int row, int p, float v) {
    g_Sh[(size_t)row*NPTS + p] = __float2half_rn(v);
}
__device__ __forceinline__ void sig_write(int rowbase, int p,
                                          const float S1[4], const float S2[16],
                                          const float S3[64]) {
#pragma unroll
    for (int i = 0; i < 4; i++)  wr1(rowbase + i, p, S1[i]);
#pragma unroll
    for (int i = 0; i < 16; i++) wr1(rowbase + 4 + i, p, S2[i]);
#pragma unroll
    for (int i = 0; i < 64; i++) wr1(rowbase + 20 + i, p, S3[i]);
}

// ---------------- K1: signatures ----------------
__global__ void k_sig(const float* __restrict__ x, const int* __restrict__ path) {
    int p = blockIdx.x * blockDim.x + threadIdx.x;
    if (p >= NPTS) return;
    int t  = p & (TT - 1);
    int bj = p >> 9;
    int j  = bj % JJ;
    int b  = bj / JJ;
    const float* xb = x + (size_t)b * CC * JJ * TT;

    float S1[4], S2[16], S3[64];
    float prev[3], cur[3], d[4];

#pragma unroll
    for (int i = 0; i < 4; i++)  S1[i] = 0.f;
#pragma unroll
    for (int i = 0; i < 16; i++) S2[i] = 0.f;
#pragma unroll
    for (int i = 0; i < 64; i++) S3[i] = 0.f;

    int j0 = path[j*3+0], j1 = path[j*3+1], j2 = path[j*3+2];
#pragma unroll
    for (int c = 0; c < 3; c++) prev[c] = xb[(c*JJ + j0)*TT + t];
    d[0] = 0.f; d[1] = prev[0]; d[2] = prev[1]; d[3] = prev[2];
    sig_step(S1, S2, S3, d);
#pragma unroll
    for (int c = 0; c < 3; c++) cur[c] = xb[(c*JJ + j1)*TT + t];
    d[0] = 0.5f;
#pragma unroll
    for (int c = 0; c < 3; c++) { d[c+1] = cur[c] - prev[c]; prev[c] = cur[c]; }
    sig_step(S1, S2, S3, d);
#pragma unroll
    for (int c = 0; c < 3; c++) cur[c] = xb[(c*JJ + j2)*TT + t];
    d[0] = 0.5f;
#pragma unroll
    for (int c = 0; c < 3; c++) d[c+1] = cur[c] - prev[c];
    sig_step(S1, S2, S3, d);
    sig_write(0, p, S1, S2, S3);

#pragma unroll
    for (int i = 0; i < 4; i++)  S1[i] = 0.f;
#pragma unroll
    for (int i = 0; i < 16; i++) S2[i] = 0.f;
#pragma unroll
    for (int i = 0; i < 64; i++) S3[i] = 0.f;

#pragma unroll
    for (int l = 0; l < 7; l++) {
        int tc = t + l - 3;
        tc = tc < 0 ? 0 : (tc > TT-1 ? TT-1 : tc);
#pragma unroll
        for (int c = 0; c < 3; c++) cur[c] = xb[(c*JJ + j)*TT + tc];
        if (l == 0) {
            d[0] = 0.f;
#pragma unroll
            for (int c = 0; c < 3; c++) d[c+1] = cur[c];
        } else {
            d[0] = 1.0f/6.0f;
#pragma unroll
            for (int c = 0; c < 3; c++) d[c+1] = cur[c] - prev[c];
        }
#pragma unroll
        for (int c = 0; c < 3; c++) prev[c] = cur[c];
        sig_step(S1, S2, S3, d);
    }
    sig_write(SIGC, p, S1, S2, S3);
}

// ---------------- K2: raw conv + bias -> U fp16 + fused BN partials ----------------
__global__ void k_raw(const float* __restrict__ x, const float* __restrict__ w,
                      const float* __restrict__ b) {
    __shared__ float xs[3][TT + 2];
    __shared__ float ws[CO * 9];
    __shared__ float bs[CO];
    int bj = blockIdx.x;
    int j = bj % JJ, bb = bj / JJ;
    int tid = threadIdx.x;
    int warp = tid >> 5, lane = tid & 31;

    for (int i = tid; i < 3*(TT+2); i += 256) {
        int c = i / (TT+2), tt = i % (TT+2);
        xs[c][tt] = (tt >= 1 && tt <= TT) ? x[((bb*3 + c)*JJ + j)*TT + tt - 1] : 0.f;
    }
    for (int i = tid; i < CO*9; i += 256) ws[i] = w[i];
    if (tid < CO) bs[tid] = b[tid];
    __syncthreads();

    int pbase = bj * TT;
#pragma unroll 1
    for (int oi = 0; oi < 16; oi++) {
        int o = warp*16 + oi;
        float wr[9];
#pragma unroll
        for (int i = 0; i < 9; i++) wr[i] = ws[o*9 + i];
        float bo = bs[o];
        float s = 0.f, q = 0.f;
        __half* orow = g_UVh + (size_t)o*NPTS + pbase;
#pragma unroll
        for (int i = 0; i < 16; i++) {
            int t = i*32 + lane;
            float a = bo;
#pragma unroll
            for (int c = 0; c < 3; c++)
#pragma unroll
                for (int kw = 0; kw < 3; kw++)
                    a = fmaf(xs[c][t + kw], wr[c*3 + kw], a);
            orow[t] = __float2half_rn(a);
            s += a; q += a*a;
        }
#pragma unroll
        for (int d = 16; d; d >>= 1) {
            s += __shfl_xor_sync(0xffffffffu, s, d);
            q += __shfl_xor_sync(0xffffffffu, q, d);
        }
        if (lane == 0) { g_pU[bj*CO + o] = s; g_pUQ[bj*CO + o] = q; }
    }
}

// ---------------- prep: fp16 A fragment images (m16n8k16 layout, per kc32) ----------------
__global__ void k_prep(const float* __restrict__ psw, const float* __restrict__ fusw) {
    int which = blockIdx.x;
    const float* W = which ? fusw : psw;
    int K = which ? K2A : K1A;
    int nslot = which ? 8*512 : 6*512;
    uint4* A = which ? g_Afus : g_Aps;
    for (int s = threadIdx.x; s < nslot; s += blockDim.x) {
        int lane = s & 31, ks = (s >> 5) & 1, g = (s >> 6) & 7, kc = s >> 9;
        int r = g*16 + (lane >> 2);
        int kb = kc*32 + ks*16 + 2*(lane & 3);
        float a00 = (kb   < K) ? W[r*K + kb]       : 0.f;
        float a01 = (kb+1 < K) ? W[r*K + kb+1]     : 0.f;
        float a10 = (kb   < K) ? W[(r+8)*K + kb]   : 0.f;
        float a11 = (kb+1 < K) ? W[(r+8)*K + kb+1] : 0.f;
        float a20 = (kb+8 < K) ? W[r*K + kb+8]     : 0.f;
        float a21 = (kb+9 < K) ? W[r*K + kb+9]     : 0.f;
        float a30 = (kb+8 < K) ? W[(r+8)*K + kb+8] : 0.f;
        float a31 = (kb+9 < K) ? W[(r+8)*K + kb+9] : 0.f;
        A[s] = make_uint4(packh2(a00, a01), packh2(a10, a11),
                          packh2(a20, a21), packh2(a30, a31));
    }
}

// ---------------- GEMM building blocks (KS=64 chunks) ----------------
__device__ __forceinline__ void issueA(int c, int tid, uint32_t sb, const uint4* Aimg) {
#pragma unroll
    for (int i = 0; i < 4; i++) {
        int m = tid + i*256;       // 1024 slots = 2 kc32 images
        cp16(sb + OFF_A(c & 1) + m*16, Aimg + c*1024 + m, 16);
    }
}
__device__ __forceinline__ void issueB0(int c, int tid, uint32_t sb, int p0) {
#pragma unroll
    for (int i = 0; i < 4; i++) {
        int m = tid + i*256;
        int kl = m >> 4, seg = m & 15;   // kl 0..63
        int kg = c*KS + kl;
        int ok = kg < K1A;
        const __half* src = g_Sh + (size_t)(ok ? kg : 0)*NPTS + p0 + seg*8;
        cp16(sb + OFF_B(c & 1) + kl*272 + seg*16, src, ok ? 16u : 0u);
    }
}
__device__ __forceinline__ void issueRaw(int c, int tid, uint32_t sb, int p0) {
#pragma unroll
    for (int i = 0; i < 4; i++) {
        int m = tid + i*256;
        int kl = m >> 4;
        const __half* src = g_UVh + (size_t)(c*KS + kl)*NPTS + p0 + (m & 15)*8;
        cp16(sb + OFF_RAW(c & 1) + m*16, src, 16);
    }
}
// affine+relu on fus chunk cc: raw[cc&1] (fp16) -> B[cc&1] (fp16)
__device__ __forceinline__ void convF(int cc, int tid, char* smc,
        const float* s_sc, const float* s_bi) {
    const char* raw = smc + OFF_RAW(cc & 1);
    char* B = smc + OFF_B(cc & 1);
#pragma unroll
    for (int i = 0; i < 4; i++) {
        int m = tid + i*256;
        int kl = m >> 4, seg = m & 15;
        uint4 v = *(const uint4*)(raw + m*16);
        int kg = cc*KS + kl;
        float sc = s_sc[kg], bi = s_bi[kg];
        uint4 o;
        uint32_t* vp = (uint32_t*)&v;
        uint32_t* op = (uint32_t*)&o;
#pragma unroll
        for (int q = 0; q < 4; q++) {
            float2 f = __half22float2(*(__half2*)&vp[q]);
            f.x = fmaxf(fmaf(f.x, sc, bi), 0.f);
            f.y = fmaxf(fmaf(f.y, sc, bi), 0.f);
            op[q] = packh2(f.x, f.y);
        }
        *(uint4*)(B + kl*272 + seg*16) = o;
    }
}

// ---------------- pipelined fp16 GEMM: D[128ch][128pts]/CTA, 256 thr, 2 CTA/SM ----------------
__global__ void __launch_bounds__(256, 2) k_gemm_tc(int mode, const float* __restrict__ bias) {
    extern __shared__ char smc[];
    __shared__ float sS[CO], sQ[CO];
    uint32_t sb = smem_u32(smc);
    float* s_sc = (float*)(smc + OFF_SC);
    float* s_bi = (float*)(smc + OFF_BI);

    int tid = threadIdx.x;
    int warp = tid >> 5, lane = tid & 31;
    int wm = (warp >> 2) * 64;
    int wn = (warp & 3) * 32;
    int gbase = (warp >> 2) * 4;
    int lq = lane >> 2, lr = lane & 3;
    int p0 = blockIdx.x * NT;

    int kchunks = mode ? 4 : 3;
    const uint4* Aimg = mode ? g_Afus : g_Aps;
    __half* Out = mode ? g_Fh : (g_UVh + (size_t)CO*NPTS);
    float* pS  = mode ? g_pF : g_pV;
    float* pQ  = mode ? g_pFQ : g_pVQ;

    if (mode)
        for (int i = tid; i < K2A; i += 256) { s_sc[i] = g_sc1[i]; s_bi[i] = g_bi1[i]; }
    if (tid < CO) { sS[tid] = 0.f; sQ[tid] = 0.f; }
    __syncthreads();

    float acc[4][4][4];
#pragma unroll
    for (int i = 0; i < 4; i++)
#pragma unroll
        for (int j = 0; j < 4; j++)
#pragma unroll
            for (int r = 0; r < 4; r++) acc[i][j][r] = 0.f;

    // ---- prologue ----
    issueA(0, tid, sb, Aimg);
    if (mode) issueRaw(0, tid, sb, p0); else issueB0(0, tid, sb, p0);
    CP_COMMIT();
    issueA(1, tid, sb, Aimg);
    if (mode) issueRaw(1, tid, sb, p0); else issueB0(1, tid, sb, p0);
    CP_COMMIT();
    CP_WAIT1();
    if (mode) convF(0, tid, smc, s_sc, s_bi);
    __syncthreads();

    for (int c = 0; c < kchunks; c++) {
        int s = c & 1;
        const char* As = smc + OFF_A(s);
        // ---- MMA chunk c: 4 k16 steps ----
#pragma unroll
        for (int ks = 0; ks < 4; ks++) {
            const char* Ak = As + (ks >> 1)*8192;
            uint4 af[4];
#pragma unroll
            for (int i = 0; i < 4; i++)
                af[i] = *(const uint4*)(Ak + (gbase + i)*1024 + (ks & 1)*512 + lane*16);
#pragma unroll
            for (int j = 0; j < 4; j++) {
                uint32_t b[2];
                uint32_t boff = (uint32_t)((ks*16 + (lane & 15))*272 + (wn + j*8)*2);
                ldsm_x2_t(b, sb + OFF_B(s) + boff);
#pragma unroll
                for (int i = 0; i < 4; i++)
                    mma_f16(acc[i][j], af[i], b[0], b[1]);
            }
        }
        __syncthreads();       // MMA(c) reads done; stage c&1 reusable
        if (c + 2 < kchunks) {
            issueA(c+2, tid, sb, Aimg);
            if (mode) issueRaw(c+2, tid, sb, p0); else issueB0(c+2, tid, sb, p0);
        }
        CP_COMMIT();
        CP_WAIT1();            // stage (c+1) arrived
        if (mode && c + 1 < kchunks) convF(c+1, tid, smc, s_sc, s_bi);
        __syncthreads();
    }

    // ---- epilogue: bias, store fp16 channel-major, fused BN partials ----
#pragma unroll
    for (int i = 0; i < 4; i++) {
        int c0 = wm + i*16 + lq;
        int c1 = c0 + 8;
        float b0 = bias[c0], b1 = bias[c1];
        float s0 = 0.f, q0 = 0.f, s1 = 0.f, q1 = 0.f;
#pragma unroll
        for (int j = 0; j < 4; j++) {
            float v00 = acc[i][j][0] + b0, v01 = acc[i][j][1] + b0;
            float v10 = acc[i][j][2] + b1, v11 = acc[i][j][3] + b1;
            int p = p0 + wn + j*8 + (lr << 1);
            __half2 h0 = __floats2half2_rn(v00, v01);
            __half2 h1 = __floats2half2_rn(v10, v11);
            *(__half2*)&Out[(size_t)c0*NPTS + p] = h0;
            *(__half2*)&Out[(size_t)c1*NPTS + p] = h1;
            s0 += v00 + v01; q0 += v00*v00 + v01*v01;
            s1 += v10 + v11; q1 += v10*v10 + v11*v11;
        }
#pragma unroll
        for (int d = 1; d < 4; d <<= 1) {
            s0 += __shfl_xor_sync(0xffffffffu, s0, d);
            q0 += __shfl_xor_sync(0xffffffffu, q0, d);
            s1 += __shfl_xor_sync(0xffffffffu, s1, d);
            q1 += __shfl_xor_sync(0xffffffffu, q1, d);
        }
        if (lr == 0) {
            atomicAdd(&sS[c0], s0); atomicAdd(&sQ[c0], q0);
            atomicAdd(&sS[c1], s1); atomicAdd(&sQ[c1], q1);
        }
    }
    __syncthreads();
    if (tid < CO) {
        pS[blockIdx.x*CO + tid] = sS[tid];
        pQ[blockIdx.x*CO + tid] = sQ[tid];
    }
}

// ---------------- finalize BN affines ----------------
__global__ void k_fin1(const float* __restrict__ rg, const float* __restrict__ rb,
                       const float* __restrict__ pg, const float* __restrict__ pb) {
    int c = blockIdx.x;   // 0..255
    float s = 0.f, q = 0.f;
    if (c < CO) {
        for (int i = threadIdx.x; i < RAWG; i += 128) { s += g_pU[i*CO + c]; q += g_pUQ[i*CO + c]; }
    } else {
        int cc = c - CO;
        for (int i = threadIdx.x; i < GRIDG; i += 128) { s += g_pV[i*CO + cc]; q += g_pVQ[i*CO + cc]; }
    }
    __shared__ float sh[256];
    sh[threadIdx.x] = s; sh[128 + threadIdx.x] = q;
    __syncthreads();
    for (int st = 64; st; st >>= 1) {
        if (threadIdx.x < st) {
            sh[threadIdx.x]       += sh[threadIdx.x + st];
            sh[128 + threadIdx.x] += sh[128 + threadIdx.x + st];
        }
        __syncthreads();
    }
    if (threadIdx.x == 0) {
        float mean = sh[0] / (float)NPTS;
        float var  = sh[128] / (float)NPTS - mean*mean;
        float rstd = rsqrtf(var + 1e-5f);
        float g  = (c < CO) ? rg[c] : pg[c - CO];
        float be = (c < CO) ? rb[c] : pb[c - CO];
        g_sc1[c] = rstd * g;
        g_bi1[c] = be - mean * rstd * g;
    }
}

__global__ void k_fin2(const float* __restrict__ fg, const float* __restrict__ fb) {
    int c = blockIdx.x;   // 0..127
    float s = 0.f, q = 0.f;
    for (int i = threadIdx.x; i < GRIDG; i += 128) { s += g_pF[i*CO + c]; q += g_pFQ[i*CO + c]; }
    __shared__ float sh[256];
    sh[threadIdx.x] = s; sh[128 + threadIdx.x] = q;
    __syncthreads();
    for (int st = 64; st; st >>= 1) {
        if (threadIdx.x < st) {
            sh[threadIdx.x]       += sh[threadIdx.x + st];
            sh[128 + threadIdx.x] += sh[128 + threadIdx.x + st];
        }
        __syncthreads();
    }
    if (threadIdx.x == 0) {
        float mean = sh[0] / (float)NPTS;
        float var  = sh[128] / (float)NPTS - mean*mean;
        float rstd = rsqrtf(var + 1e-5f);
        g_sc2[c] = rstd * fg[c];
        g_bi2[c] = fb[c] - mean * rstd * fg[c];
    }
}

// ---------------- final affine + relu + reshape (8 fp16 per thread) ----------------
__global__ void k_out(float* __restrict__ out) {
    int e8 = blockIdx.x * 256 + threadIdx.x;
    int idx = e8 << 3;
    int o = idx / NPTS;
    int p = idx - o * NPTS;
    int t  = p & (TT - 1);
    int bj = p >> 9;
    int j  = bj % JJ;
    int b  = bj / JJ;
    uint4 v = *(const uint4*)&g_Fh[idx];
    float sc = g_sc2[o], bi = g_bi2[o];
    const uint32_t* vp = (const uint32_t*)&v;
    float r[8];
#pragma unroll
    for (int q = 0; q < 4; q++) {
        float2 f = __half22float2(*(const __half2*)&vp[q]);
        r[q*2+0] = fmaxf(fmaf(f.x, sc, bi), 0.f);
        r[q*2+1] = fmaxf(fmaf(f.y, sc, bi), 0.f);
    }
    float* dst = &out[((b*CO + o)*JJ + j)*TT + t];
    *(float4*)dst       = make_float4(r[0], r[1], r[2], r[3]);
    *(float4*)(dst + 4) = make_float4(r[4], r[5], r[6], r[7]);
}

// ---------------- launcher ----------------
extern "C" void kernel_launch(void* const* d_in, const int* in_sizes, int n_in,
                              void* d_out, int out_size) {
    const float* x      = (const float*)d_in[0];
    const int*   path   = (const int*)  d_in[1];
    const float* raw_w  = (const float*)d_in[2];
    const float* raw_b  = (const float*)d_in[3];
    const float* raw_g  = (const float*)d_in[4];
    const float* raw_be = (const float*)d_in[5];
    const float* ps_w   = (const float*)d_in[6];
    const float* ps_b   = (const float*)d_in[7];
    const float* ps_g   = (const float*)d_in[8];
    const float* ps_be  = (const float*)d_in[9];
    const float* fus_w  = (const float*)d_in[10];
    const float* fus_b  = (const float*)d_in[11];
    const float* fus_g  = (const float*)d_in[12];
    const float* fus_be = (const float*)d_in[13];
    float* out = (float*)d_out;

    cudaFuncSetAttribute(k_gemm_tc, cudaFuncAttributeMaxDynamicSharedMemorySize, SMEM_GEMM);

    k_prep<<<2, 256>>>(ps_w, fus_w);
    k_sig<<<NPTS/256, 256>>>(x, path);
    k_raw<<<RAWG, 256>>>(x, raw_w, raw_b);
    k_gemm_tc<<<GRIDG, 256, SMEM_GEMM>>>(0, ps_b);
    k_fin1<<<2*CO, 128>>>(raw_g, raw_be, ps_g, ps_be);
    k_gemm_tc<<<GRIDG, 256, SMEM_GEMM>>>(1, fus_b);
    k_fin2<<<CO, 128>>>(fus_g, fus_be);
    k_out<<<(CO*NPTS)/2048, 256>>>(out);
}

// round 14
// speedup vs baseline: 1.4839x; 1.0429x over previous
#include <cuda_runtime.h>
#include <cuda_fp16.h>
#include <stdint.h>

#define BB 64
#define CC 3
#define JJ 11
#define TT 512
#define CO 128
#define NPTS (BB*JJ*TT)      /* 360448 = 2816*128 */
#define SIGC 84
#define K1A 168
#define K2A 256
#define NT 128
#define GRIDG (NPTS/NT)      /* 2816 */
#define RAWG (BB*JJ)
#define KS 64

// ---------------- static scratch ----------------
__device__ __half g_UVh[(size_t)K2A * NPTS];  // rows 0..127 = U, 128..255 = V (fp16)
__device__ __half g_Fh[(size_t)CO * NPTS];    // fus pre-BN (fp16)
__device__ uint4 g_Aps[6*512];                // fp16 A frag images ([kc32] x 512 slots)
__device__ uint4 g_Afus[8*512];
__device__ float g_pU[RAWG*CO],   g_pUQ[RAWG*CO];
__device__ float g_pV[GRIDG*CO],  g_pVQ[GRIDG*CO];
__device__ float g_pF[GRIDG*CO],  g_pFQ[GRIDG*CO];
__device__ float g_sc1[K2A], g_bi1[K2A];
__device__ float g_sc2[CO],  g_bi2[CO];

// ---------------- PTX helpers ----------------
__device__ __forceinline__ uint32_t smem_u32(const void* p) {
    uint32_t a;
    asm("{ .reg .u64 t; cvta.to.shared.u64 t, %1; cvt.u32.u64 %0, t; }" : "=r"(a) : "l"(p));
    return a;
}
__device__ __forceinline__ void ldsm_x2_t(uint32_t (&r)[2], uint32_t addr) {
    asm volatile("ldmatrix.sync.aligned.m8n8.x2.trans.shared.b16 {%0,%1}, [%2];"
        : "=r"(r[0]), "=r"(r[1]) : "r"(addr));
}
__device__ __forceinline__ void mma_f16(float (&d)[4], const uint4& a,
                                        uint32_t b0, uint32_t b1) {
    asm volatile("mma.sync.aligned.m16n8k16.row.col.f32.f16.f16.f32 "
        "{%0,%1,%2,%3}, {%4,%5,%6,%7}, {%8,%9}, {%0,%1,%2,%3};"
        : "+f"(d[0]), "+f"(d[1]), "+f"(d[2]), "+f"(d[3])
        : "r"(a.x), "r"(a.y), "r"(a.z), "r"(a.w), "r"(b0), "r"(b1));
}
__device__ __forceinline__ void cp16(uint32_t dst, const void* src, uint32_t sz) {
    asm volatile("cp.async.cg.shared.global [%0], [%1], 16, %2;"
        :: "r"(dst), "l"(src), "r"(sz));
}
#define CP_COMMIT() asm volatile("cp.async.commit_group;")
#define CP_WAIT0()  asm volatile("cp.async.wait_group 0;")
#define CP_WAIT1()  asm volatile("cp.async.wait_group 1;")

__device__ __forceinline__ uint32_t packh2(float a, float b) {
    __half2 h = __floats2half2_rn(a, b);
    return *(uint32_t*)&h;
}

// ---- SMEM layouts ----
// k_sigps: B full tile 192 rows x 272B = 52224; A 3 chunks x 16KB = 49152
#define PS_B    0
#define PS_A    52224
#define SMEM_PS 101376
// k_fus (same as R13 mode-1):
#define OFF_A(s)   ((s)*16384)
#define OFF_B(s)   (32768 + (s)*17408)
#define OFF_RAW(s) (67584 + (s)*16384)
#define OFF_SC 100352
#define OFF_BI 101376
#define SMEM_FUS 102400

// ---------------- depth-3 signature Chen step (c = 4) ----------------
__device__ __forceinline__ void sig_step(float S1[4], float S2[16], float S3[64],
                                         const float d[4]) {
    float dd[16];
#pragma unroll
    for (int i = 0; i < 4; i++)
#pragma unroll
        for (int j = 0; j < 4; j++) dd[i*4+j] = d[i]*d[j];
    float a[4];
#pragma unroll
    for (int i = 0; i < 4; i++) a[i] = 0.5f*S1[i] + d[i]*(1.0f/6.0f);
#pragma unroll
    for (int i = 0; i < 4; i++)
#pragma unroll
        for (int j = 0; j < 4; j++)
#pragma unroll
            for (int k = 0; k < 4; k++)
                S3[i*16+j*4+k] += S2[i*4+j]*d[k] + a[i]*dd[j*4+k];
#pragma unroll
    for (int i = 0; i < 4; i++)
#pragma unroll
        for (int j = 0; j < 4; j++)
            S2[i*4+j] += S1[i]*d[j] + 0.5f*dd[i*4+j];
#pragma unroll
    for (int i = 0; i < 4; i++) S1[i] += d[i];
}

// ---------------- K2: raw conv + bias -> U fp16 + fused BN partials ----------------
__global__ void k_raw(const float* __restrict__ x, const float* __restrict__ w,
                      const float* __restrict__ b) {
    __shared__ float xs[3][TT + 2];
    __shared__ float ws[CO * 9];
    __shared__ float bs[CO];
    int bj = blockIdx.x;
    int j = bj % JJ, bb = bj / JJ;
    int tid = threadIdx.x;
    int warp = tid >> 5, lane = tid & 31;

    for (int i = tid; i < 3*(TT+2); i += 256) {
        int c = i / (TT+2), tt = i % (TT+2);
        xs[c][tt] = (tt >= 1 && tt <= TT) ? x[((bb*3 + c)*JJ + j)*TT + tt - 1] : 0.f;
    }
    for (int i = tid; i < CO*9; i += 256) ws[i] = w[i];
    if (tid < CO) bs[tid] = b[tid];
    __syncthreads();

    int pbase = bj * TT;
#pragma unroll 1
    for (int oi = 0; oi < 16; oi++) {
        int o = warp*16 + oi;
        float wr[9];
#pragma unroll
        for (int i = 0; i < 9; i++) wr[i] = ws[o*9 + i];
        float bo = bs[o];
        float s = 0.f, q = 0.f;
        __half* orow = g_UVh + (size_t)o*NPTS + pbase;
#pragma unroll
        for (int i = 0; i < 16; i++) {
            int t = i*32 + lane;
            float a = bo;
#pragma unroll
            for (int c = 0; c < 3; c++)
#pragma unroll
                for (int kw = 0; kw < 3; kw++)
                    a = fmaf(xs[c][t + kw], wr[c*3 + kw], a);
            orow[t] = __float2half_rn(a);
            s += a; q += a*a;
        }
#pragma unroll
        for (int d = 16; d; d >>= 1) {
            s += __shfl_xor_sync(0xffffffffu, s, d);
            q += __shfl_xor_sync(0xffffffffu, q, d);
        }
        if (lane == 0) { g_pU[bj*CO + o] = s; g_pUQ[bj*CO + o] = q; }
    }
}

// ---------------- prep: fp16 A fragment images (m16n8k16 layout, per kc32) ----------------
__global__ void k_prep(const float* __restrict__ psw, const float* __restrict__ fusw) {
    int which = blockIdx.x;
    const float* W = which ? fusw : psw;
    int K = which ? K2A : K1A;
    int nslot = which ? 8*512 : 6*512;
    uint4* A = which ? g_Afus : g_Aps;
    for (int s = threadIdx.x; s < nslot; s += blockDim.x) {
        int lane = s & 31, ks = (s >> 5) & 1, g = (s >> 6) & 7, kc = s >> 9;
        int r = g*16 + (lane >> 2);
        int kb = kc*32 + ks*16 + 2*(lane & 3);
        float a00 = (kb   < K) ? W[r*K + kb]       : 0.f;
        float a01 = (kb+1 < K) ? W[r*K + kb+1]     : 0.f;
        float a10 = (kb   < K) ? W[(r+8)*K + kb]   : 0.f;
        float a11 = (kb+1 < K) ? W[(r+8)*K + kb+1] : 0.f;
        float a20 = (kb+8 < K) ? W[r*K + kb+8]     : 0.f;
        float a21 = (kb+9 < K) ? W[r*K + kb+9]     : 0.f;
        float a30 = (kb+8 < K) ? W[(r+8)*K + kb+8] : 0.f;
        float a31 = (kb+9 < K) ? W[(r+8)*K + kb+9] : 0.f;
        A[s] = make_uint4(packh2(a00, a01), packh2(a10, a11),
                          packh2(a20, a21), packh2(a30, a31));
    }
}

// ---------------- fused signature + ps GEMM ----------------
__global__ void __launch_bounds__(256, 2) k_sigps(
        const float* __restrict__ x, const int* __restrict__ path,
        const float* __restrict__ bias) {
    extern __shared__ char smc[];
    __shared__ float sS[CO], sQ[CO];
    uint32_t sb = smem_u32(smc);
    int tid = threadIdx.x;
    int warp = tid >> 5, lane = tid & 31;
    int wm = (warp >> 2) * 64;
    int wn = (warp & 3) * 32;
    int gbase = (warp >> 2) * 4;
    int lq = lane >> 2, lr = lane & 3;
    int p0 = blockIdx.x * NT;

    // prefetch ALL A chunks (48KB) in one group
#pragma unroll
    for (int i = 0; i < 12; i++) {
        int m = tid + i*256;   // 3072 slots
        cp16(sb + PS_A + m*16, g_Aps + m, 16);
    }
    CP_COMMIT();

    if (tid < CO) { sS[tid] = 0.f; sQ[tid] = 0.f; }
    // zero padded B rows 168..191
    for (int i = tid; i < 24*136; i += 256) {
        int row = 168 + i/136, col = i % 136;
        *(__half*)(smc + PS_B + row*272 + col*2) = __float2half_rn(0.f);
    }

    // ---- phase 1: signatures -> B SMEM column pp ----
    {
        int pp = tid & 127;
        int which = tid >> 7;          // 0 = spatial, 1 = temporal
        int p = p0 + pp;
        int t  = p & (TT - 1);
        int bj = p >> 9;
        int j  = bj % JJ;
        int b  = bj / JJ;
        const float* xb = x + (size_t)b * CC * JJ * TT;

        float S1[4], S2[16], S3[64];
        float prev[3], cur[3], d[4];
#pragma unroll
        for (int i = 0; i < 4; i++)  S1[i] = 0.f;
#pragma unroll
        for (int i = 0; i < 16; i++) S2[i] = 0.f;
#pragma unroll
        for (int i = 0; i < 64; i++) S3[i] = 0.f;

        if (which == 0) {
            int j0 = path[j*3+0], j1 = path[j*3+1], j2 = path[j*3+2];
#pragma unroll
            for (int c = 0; c < 3; c++) prev[c] = xb[(c*JJ + j0)*TT + t];
            d[0] = 0.f; d[1] = prev[0]; d[2] = prev[1]; d[3] = prev[2];
            sig_step(S1, S2, S3, d);
#pragma unroll
            for (int c = 0; c < 3; c++) cur[c] = xb[(c*JJ + j1)*TT + t];
            d[0] = 0.5f;
#pragma unroll
            for (int c = 0; c < 3; c++) { d[c+1] = cur[c] - prev[c]; prev[c] = cur[c]; }
            sig_step(S1, S2, S3, d);
#pragma unroll
            for (int c = 0; c < 3; c++) cur[c] = xb[(c*JJ + j2)*TT + t];
            d[0] = 0.5f;
#pragma unroll
            for (int c = 0; c < 3; c++) d[c+1] = cur[c] - prev[c];
            sig_step(S1, S2, S3, d);
        } else {
#pragma unroll
            for (int l = 0; l < 7; l++) {
                int tc = t + l - 3;
                tc = tc < 0 ? 0 : (tc > TT-1 ? TT-1 : tc);
#pragma unroll
                for (int c = 0; c < 3; c++) cur[c] = xb[(c*JJ + j)*TT + tc];
                if (l == 0) {
                    d[0] = 0.f;
#pragma unroll
                    for (int c = 0; c < 3; c++) d[c+1] = cur[c];
                } else {
                    d[0] = 1.0f/6.0f;
#pragma unroll
                    for (int c = 0; c < 3; c++) d[c+1] = cur[c] - prev[c];
                }
#pragma unroll
                for (int c = 0; c < 3; c++) prev[c] = cur[c];
                sig_step(S1, S2, S3, d);
            }
        }
        // write 84 rows at rowbase = which*84, column pp
        char* B = smc + PS_B;
        int rowbase = which * SIGC;
#pragma unroll
        for (int i = 0; i < 4; i++)
            *(__half*)(B + (rowbase + i)*272 + pp*2) = __float2half_rn(S1[i]);
#pragma unroll
        for (int i = 0; i < 16; i++)
            *(__half*)(B + (rowbase + 4 + i)*272 + pp*2) = __float2half_rn(S2[i]);
#pragma unroll
        for (int i = 0; i < 64; i++)
            *(__half*)(B + (rowbase + 20 + i)*272 + pp*2) = __float2half_rn(S3[i]);
    }

    CP_WAIT0();
    __syncthreads();          // B complete + A visible

    // ---- phase 2: MMA, 3 chunks of K=64, no in-loop barriers ----
    float acc[4][4][4];
#pragma unroll
    for (int i = 0; i < 4; i++)
#pragma unroll
        for (int j = 0; j < 4; j++)
#pragma unroll
            for (int r = 0; r < 4; r++) acc[i][j][r] = 0.f;

#pragma unroll 1
    for (int c = 0; c < 3; c++) {
        const char* Ac = smc + PS_A + c*16384;
#pragma unroll
        for (int ks = 0; ks < 4; ks++) {
            const char* Ak = Ac + (ks >> 1)*8192;
            uint4 af[4];
#pragma unroll
            for (int i = 0; i < 4; i++)
                af[i] = *(const uint4*)(Ak + (gbase + i)*1024 + (ks & 1)*512 + lane*16);
#pragma unroll
            for (int j = 0; j < 4; j++) {
                uint32_t b[2];
                uint32_t boff = (uint32_t)((c*64 + ks*16 + (lane & 15))*272 + (wn + j*8)*2);
                ldsm_x2_t(b, sb + PS_B + boff);
#pragma unroll
                for (int i = 0; i < 4; i++)
                    mma_f16(acc[i][j], af[i], b[0], b[1]);
            }
        }
    }

    // ---- epilogue: bias, store V fp16 channel-major, fused BN partials ----
    __half* Out = g_UVh + (size_t)CO*NPTS;
#pragma unroll
    for (int i = 0; i < 4; i++) {
        int c0 = wm + i*16 + lq;
        int c1 = c0 + 8;
        float b0 = bias[c0], b1 = bias[c1];
        float s0 = 0.f, q0 = 0.f, s1 = 0.f, q1 = 0.f;
#pragma unroll
        for (int j = 0; j < 4; j++) {
            float v00 = acc[i][j][0] + b0, v01 = acc[i][j][1] + b0;
            float v10 = acc[i][j][2] + b1, v11 = acc[i][j][3] + b1;
            int p = p0 + wn + j*8 + (lr << 1);
            *(__half2*)&Out[(size_t)c0*NPTS + p] = __floats2half2_rn(v00, v01);
            *(__half2*)&Out[(size_t)c1*NPTS + p] = __floats2half2_rn(v10, v11);
            s0 += v00 + v01; q0 += v00*v00 + v01*v01;
            s1 += v10 + v11; q1 += v10*v10 + v11*v11;
        }
#pragma unroll
        for (int d = 1; d < 4; d <<= 1) {
            s0 += __shfl_xor_sync(0xffffffffu, s0, d);
            q0 += __shfl_xor_sync(0xffffffffu, q0, d);
            s1 += __shfl_xor_sync(0xffffffffu, s1, d);
            q1 += __shfl_xor_sync(0xffffffffu, q1, d);
        }
        if (lr == 0) {
            atomicAdd(&sS[c0], s0); atomicAdd(&sQ[c0], q0);
            atomicAdd(&sS[c1], s1); atomicAdd(&sQ[c1], q1);
        }
    }
    __syncthreads();
    if (tid < CO) {
        g_pV[blockIdx.x*CO + tid]  = sS[tid];
        g_pVQ[blockIdx.x*CO + tid] = sQ[tid];
    }
}

// ---------------- fus GEMM building blocks (KS=64) ----------------
__device__ __forceinline__ void issueAf(int c, int tid, uint32_t sb) {
#pragma unroll
    for (int i = 0; i < 4; i++) {
        int m = tid + i*256;
        cp16(sb + OFF_A(c & 1) + m*16, g_Afus + c*1024 + m, 16);
    }
}
__device__ __forceinline__ void issueRaw(int c, int tid, uint32_t sb, int p0) {
#pragma unroll
    for (int i = 0; i < 4; i++) {
        int m = tid + i*256;
        int kl = m >> 4;
        const __half* src = g_UVh + (size_t)(c*KS + kl)*NPTS + p0 + (m & 15)*8;
        cp16(sb + OFF_RAW(c & 1) + m*16, src, 16);
    }
}
__device__ __forceinline__ void convF(int cc, int tid, char* smc,
        const float* s_sc, const float* s_bi) {
    const char* raw = smc + OFF_RAW(cc & 1);
    char* B = smc + OFF_B(cc & 1);
#pragma unroll
    for (int i = 0; i < 4; i++) {
        int m = tid + i*256;
        int kl = m >> 4, seg = m & 15;
        uint4 v = *(const uint4*)(raw + m*16);
        int kg = cc*KS + kl;
        float sc = s_sc[kg], bi = s_bi[kg];
        uint4 o;
        uint32_t* vp = (uint32_t*)&v;
        uint32_t* op = (uint32_t*)&o;
#pragma unroll
        for (int q = 0; q < 4; q++) {
            float2 f = __half22float2(*(__half2*)&vp[q]);
            f.x = fmaxf(fmaf(f.x, sc, bi), 0.f);
            f.y = fmaxf(fmaf(f.y, sc, bi), 0.f);
            op[q] = packh2(f.x, f.y);
        }
        *(uint4*)(B + kl*272 + seg*16) = o;
    }
}

// ---------------- pipelined fus GEMM ----------------
__global__ void __launch_bounds__(256, 2) k_fus(const float* __restrict__ bias) {
    extern __shared__ char smc[];
    __shared__ float sS[CO], sQ[CO];
    uint32_t sb = smem_u32(smc);
    float* s_sc = (float*)(smc + OFF_SC);
    float* s_bi = (float*)(smc + OFF_BI);

    int tid = threadIdx.x;
    int warp = tid >> 5, lane = tid & 31;
    int wm = (warp >> 2) * 64;
    int wn = (warp & 3) * 32;
    int gbase = (warp >> 2) * 4;
    int lq = lane >> 2, lr = lane & 3;
    int p0 = blockIdx.x * NT;

    for (int i = tid; i < K2A; i += 256) { s_sc[i] = g_sc1[i]; s_bi[i] = g_bi1[i]; }
    if (tid < CO) { sS[tid] = 0.f; sQ[tid] = 0.f; }
    __syncthreads();

    float acc[4][4][4];
#pragma unroll
    for (int i = 0; i < 4; i++)
#pragma unroll
        for (int j = 0; j < 4; j++)
#pragma unroll
            for (int r = 0; r < 4; r++) acc[i][j][r] = 0.f;

    issueAf(0, tid, sb); issueRaw(0, tid, sb, p0); CP_COMMIT();
    issueAf(1, tid, sb); issueRaw(1, tid, sb, p0); CP_COMMIT();
    CP_WAIT1();
    convF(0, tid, smc, s_sc, s_bi);
    __syncthreads();

    for (int c = 0; c < 4; c++) {
        int s = c & 1;
        const char* As = smc + OFF_A(s);
#pragma unroll
        for (int ks = 0; ks < 4; ks++) {
            const char* Ak = As + (ks >> 1)*8192;
            uint4 af[4];
#pragma unroll
            for (int i = 0; i < 4; i++)
                af[i] = *(const uint4*)(Ak + (gbase + i)*1024 + (ks & 1)*512 + lane*16);
#pragma unroll
            for (int j = 0; j < 4; j++) {
                uint32_t b[2];
                uint32_t boff = (uint32_t)((ks*16 + (lane & 15))*272 + (wn + j*8)*2);
                ldsm_x2_t(b, sb + OFF_B(s) + boff);
#pragma unroll
                for (int i = 0; i < 4; i++)
                    mma_f16(acc[i][j], af[i], b[0], b[1]);
            }
        }
        __syncthreads();
        if (c + 2 < 4) { issueAf(c+2, tid, sb); issueRaw(c+2, tid, sb, p0); }
        CP_COMMIT();
        CP_WAIT1();
        if (c + 1 < 4) convF(c+1, tid, smc, s_sc, s_bi);
        __syncthreads();
    }

    // ---- epilogue ----
#pragma unroll
    for (int i = 0; i < 4; i++) {
        int c0 = wm + i*16 + lq;
        int c1 = c0 + 8;
        float b0 = bias[c0], b1 = bias[c1];
        float s0 = 0.f, q0 = 0.f, s1 = 0.f, q1 = 0.f;
#pragma unroll
        for (int j = 0; j < 4; j++) {
            float v00 = acc[i][j][0] + b0, v01 = acc[i][j][1] + b0;
            float v10 = acc[i][j][2] + b1, v11 = acc[i][j][3] + b1;
            int p = p0 + wn + j*8 + (lr << 1);
            *(__half2*)&g_Fh[(size_t)c0*NPTS + p] = __floats2half2_rn(v00, v01);
            *(__half2*)&g_Fh[(size_t)c1*NPTS + p] = __floats2half2_rn(v10, v11);
            s0 += v00 + v01; q0 += v00*v00 + v01*v01;
            s1 += v10 + v11; q1 += v10*v10 + v11*v11;
        }
#pragma unroll
        for (int d = 1; d < 4; d <<= 1) {
            s0 += __shfl_xor_sync(0xffffffffu, s0, d);
            q0 += __shfl_xor_sync(0xffffffffu, q0, d);
            s1 += __shfl_xor_sync(0xffffffffu, s1, d);
            q1 += __shfl_xor_sync(0xffffffffu, q1, d);
        }
        if (lr == 0) {
            atomicAdd(&sS[c0], s0); atomicAdd(&sQ[c0], q0);
            atomicAdd(&sS[c1], s1); atomicAdd(&sQ[c1], q1);
        }
    }
    __syncthreads();
    if (tid < CO) {
        g_pF[blockIdx.x*CO + tid]  = sS[tid];
        g_pFQ[blockIdx.x*CO + tid] = sQ[tid];
    }
}

// ---------------- finalize BN affines ----------------
__global__ void k_fin1(const float* __restrict__ rg, const float* __restrict__ rb,
                       const float* __restrict__ pg, const float* __restrict__ pb) {
    int c = blockIdx.x;   // 0..255
    float s = 0.f, q = 0.f;
    if (c < CO) {
        for (int i = threadIdx.x; i < RAWG; i += 128) { s += g_pU[i*CO + c]; q += g_pUQ[i*CO + c]; }
    } else {
        int cc = c - CO;
        for (int i = threadIdx.x; i < GRIDG; i += 128) { s += g_pV[i*CO + cc]; q += g_pVQ[i*CO + cc]; }
    }
    __shared__ float sh[256];
    sh[threadIdx.x] = s; sh[128 + threadIdx.x] = q;
    __syncthreads();
    for (int st = 64; st; st >>= 1) {
        if (threadIdx.x < st) {
            sh[threadIdx.x]       += sh[threadIdx.x + st];
            sh[128 + threadIdx.x] += sh[128 + threadIdx.x + st];
        }
        __syncthreads();
    }
    if (threadIdx.x == 0) {
        float mean = sh[0] / (float)NPTS;
        float var  = sh[128] / (float)NPTS - mean*mean;
        float rstd = rsqrtf(var + 1e-5f);
        float g  = (c < CO) ? rg[c] : pg[c - CO];
        float be = (c < CO) ? rb[c] : pb[c - CO];
        g_sc1[c] = rstd * g;
        g_bi1[c] = be - mean * rstd * g;
    }
}

__global__ void k_fin2(const float* __restrict__ fg, const float* __restrict__ fb) {
    int c = blockIdx.x;   // 0..127
    float s = 0.f, q = 0.f;
    for (int i = threadIdx.x; i < GRIDG; i += 128) { s += g_pF[i*CO + c]; q += g_pFQ[i*CO + c]; }
    __shared__ float sh[256];
    sh[threadIdx.x] = s; sh[128 + threadIdx.x] = q;
    __syncthreads();
    for (int st = 64; st; st >>= 1) {
        if (threadIdx.x < st) {
            sh[threadIdx.x]       += sh[threadIdx.x + st];
            sh[128 + threadIdx.x] += sh[128 + threadIdx.x + st];
        }
        __syncthreads();
    }
    if (threadIdx.x == 0) {
        float mean = sh[0] / (float)NPTS;
        float var  = sh[128] / (float)NPTS - mean*mean;
        float rstd = rsqrtf(var + 1e-5f);
        g_sc2[c] = rstd * fg[c];
        g_bi2[c] = fb[c] - mean * rstd * fg[c];
    }
}

// ---------------- final affine + relu + reshape (8 fp16 per thread) ----------------
__global__ void k_out(float* __restrict__ out) {
    int e8 = blockIdx.x * 256 + threadIdx.x;
    int idx = e8 << 3;
    int o = idx / NPTS;
    int p = idx - o * NPTS;
    int t  = p & (TT - 1);
    int bj = p >> 9;
    int j  = bj % JJ;
    int b  = bj / JJ;
    uint4 v = *(const uint4*)&g_Fh[idx];
    float sc = g_sc2[o], bi = g_bi2[o];
    const uint32_t* vp = (const uint32_t*)&v;
    float r[8];
#pragma unroll
    for (int q = 0; q < 4; q++) {
        float2 f = __half22float2(*(const __half2*)&vp[q]);
        r[q*2+0] = fmaxf(fmaf(f.x, sc, bi), 0.f);
        r[q*2+1] = fmaxf(fmaf(f.y, sc, bi), 0.f);
    }
    float* dst = &out[((b*CO + o)*JJ + j)*TT + t];
    *(float4*)dst       = make_float4(r[0], r[1], r[2], r[3]);
    *(float4*)(dst + 4) = make_float4(r[4], r[5], r[6], r[7]);
}

// ---------------- launcher ----------------
extern "C" void kernel_launch(void* const* d_in, const int* in_sizes, int n_in,
                              void* d_out, int out_size) {
    const float* x      = (const float*)d_in[0];
    const int*   path   = (const int*)  d_in[1];
    const float* raw_w  = (const float*)d_in[2];
    const float* raw_b  = (const float*)d_in[3];
    const float* raw_g  = (const float*)d_in[4];
    const float* raw_be = (const float*)d_in[5];
    const float* ps_w   = (const float*)d_in[6];
    const float* ps_b   = (const float*)d_in[7];
    const float* ps_g   = (const float*)d_in[8];
    const float* ps_be  = (const float*)d_in[9];
    const float* fus_w  = (const float*)d_in[10];
    const float* fus_b  = (const float*)d_in[11];
    const float* fus_g  = (const float*)d_in[12];
    const float* fus_be = (const float*)d_in[13];
    float* out = (float*)d_out;

    cudaFuncSetAttribute(k_sigps, cudaFuncAttributeMaxDynamicSharedMemorySize, SMEM_PS);
    cudaFuncSetAttribute(k_fus,   cudaFuncAttributeMaxDynamicSharedMemorySize, SMEM_FUS);

    k_prep<<<2, 256>>>(ps_w, fus_w);
    k_raw<<<RAWG, 256>>>(x, raw_w, raw_b);
    k_sigps<<<GRIDG, 256, SMEM_PS>>>(x, path, ps_b);
    k_fin1<<<2*CO, 128>>>(raw_g, raw_be, ps_g, ps_be);
    k_fus<<<GRIDG, 256, SMEM_FUS>>>(fus_b);
    k_fin2<<<CO, 128>>>(fus_g, fus_be);
    k_out<<<(CO*NPTS)/2048, 256>>>(out);
}

// round 15
// speedup vs baseline: 1.4930x; 1.0062x over previous
#include <cuda_runtime.h>
#include <cuda_fp16.h>
#include <stdint.h>

#define BB 64
#define CC 3
#define JJ 11
#define TT 512
#define CO 128
#define NPTS (BB*JJ*TT)      /* 360448 = 2816*128 */
#define SIGC 84
#define K1A 168
#define K2A 256
#define NT 128
#define GRIDG (NPTS/NT)      /* 2816 */
#define RAWG (BB*JJ)
#define KS 64

// ---------------- static scratch ----------------
__device__ __half g_UVh[(size_t)K2A * NPTS];  // rows 0..127 = U, 128..255 = V (fp16)
__device__ __half g_Fh[(size_t)CO * NPTS];    // fus pre-BN (fp16)
__device__ uint4 g_Aps[6*512];                // fp16 A frag images ([kc32] x 512 slots)
__device__ uint4 g_Afus[8*512];
__device__ float g_pU[RAWG*CO],   g_pUQ[RAWG*CO];
__device__ float g_pV[GRIDG*CO],  g_pVQ[GRIDG*CO];
__device__ float g_pF[GRIDG*CO],  g_pFQ[GRIDG*CO];
__device__ float g_sc1[K2A], g_bi1[K2A];
__device__ float g_sc2[CO],  g_bi2[CO];

// ---------------- PTX helpers ----------------
__device__ __forceinline__ uint32_t smem_u32(const void* p) {
    uint32_t a;
    asm("{ .reg .u64 t; cvta.to.shared.u64 t, %1; cvt.u32.u64 %0, t; }" : "=r"(a) : "l"(p));
    return a;
}
__device__ __forceinline__ void ldsm_x2_t(uint32_t (&r)[2], uint32_t addr) {
    asm volatile("ldmatrix.sync.aligned.m8n8.x2.trans.shared.b16 {%0,%1}, [%2];"
        : "=r"(r[0]), "=r"(r[1]) : "r"(addr));
}
__device__ __forceinline__ void mma_f16(float (&d)[4], const uint4& a,
                                        uint32_t b0, uint32_t b1) {
    asm volatile("mma.sync.aligned.m16n8k16.row.col.f32.f16.f16.f32 "
        "{%0,%1,%2,%3}, {%4,%5,%6,%7}, {%8,%9}, {%0,%1,%2,%3};"
        : "+f"(d[0]), "+f"(d[1]), "+f"(d[2]), "+f"(d[3])
        : "r"(a.x), "r"(a.y), "r"(a.z), "r"(a.w), "r"(b0), "r"(b1));
}
__device__ __forceinline__ void cp16(uint32_t dst, const void* src, uint32_t sz) {
    asm volatile("cp.async.cg.shared.global [%0], [%1], 16, %2;"
        :: "r"(dst), "l"(src), "r"(sz));
}
#define CP_COMMIT() asm volatile("cp.async.commit_group;")
#define CP_WAIT0()  asm volatile("cp.async.wait_group 0;")
#define CP_WAIT1()  asm volatile("cp.async.wait_group 1;")

__device__ __forceinline__ uint32_t packh2(float a, float b) {
    __half2 h = __floats2half2_rn(a, b);
    return *(uint32_t*)&h;
}

// ---- SMEM layouts ----
// k_sigps: B full tile 192 rows x 272B = 52224; A 3 chunks x 16KB = 49152
#define PS_B    0
#define PS_A    52224
#define SMEM_PS 101376
// k_fus (same as R13 mode-1):
#define OFF_A(s)   ((s)*16384)
#define OFF_B(s)   (32768 + (s)*17408)
#define OFF_RAW(s) (67584 + (s)*16384)
#define OFF_SC 100352
#define OFF_BI 101376
#define SMEM_FUS 102400

// ---------------- depth-3 signature Chen step (c = 4) ----------------
__device__ __forceinline__ void sig_step(float S1[4], float S2[16], float S3[64],
                                         const float d[4]) {
    float dd[16];
#pragma unroll
    for (int i = 0; i < 4; i++)
#pragma unroll
        for (int j = 0; j < 4; j++) dd[i*4+j] = d[i]*d[j];
    float a[4];
#pragma unroll
    for (int i = 0; i < 4; i++) a[i] = 0.5f*S1[i] + d[i]*(1.0f/6.0f);
#pragma unroll
    for (int i = 0; i < 4; i++)
#pragma unroll
        for (int j = 0; j < 4; j++)
#pragma unroll
            for (int k = 0; k < 4; k++)
                S3[i*16+j*4+k] += S2[i*4+j]*d[k] + a[i]*dd[j*4+k];
#pragma unroll
    for (int i = 0; i < 4; i++)
#pragma unroll
        for (int j = 0; j < 4; j++)
            S2[i*4+j] += S1[i]*d[j] + 0.5f*dd[i*4+j];
#pragma unroll
    for (int i = 0; i < 4; i++) S1[i] += d[i];
}

// ---------------- K2: raw conv + bias -> U fp16 + fused BN partials ----------------
__global__ void k_raw(const float* __restrict__ x, const float* __restrict__ w,
                      const float* __restrict__ b) {
    __shared__ float xs[3][TT + 2];
    __shared__ float ws[CO * 9];
    __shared__ float bs[CO];
    int bj = blockIdx.x;
    int j = bj % JJ, bb = bj / JJ;
    int tid = threadIdx.x;
    int warp = tid >> 5, lane = tid & 31;

    for (int i = tid; i < 3*(TT+2); i += 256) {
        int c = i / (TT+2), tt = i % (TT+2);
        xs[c][tt] = (tt >= 1 && tt <= TT) ? x[((bb*3 + c)*JJ + j)*TT + tt - 1] : 0.f;
    }
    for (int i = tid; i < CO*9; i += 256) ws[i] = w[i];
    if (tid < CO) bs[tid] = b[tid];
    __syncthreads();

    int pbase = bj * TT;
#pragma unroll 1
    for (int oi = 0; oi < 16; oi++) {
        int o = warp*16 + oi;
        float wr[9];
#pragma unroll
        for (int i = 0; i < 9; i++) wr[i] = ws[o*9 + i];
        float bo = bs[o];
        float s = 0.f, q = 0.f;
        __half* orow = g_UVh + (size_t)o*NPTS + pbase;
#pragma unroll
        for (int i = 0; i < 16; i++) {
            int t = i*32 + lane;
            float a = bo;
#pragma unroll
            for (int c = 0; c < 3; c++)
#pragma unroll
                for (int kw = 0; kw < 3; kw++)
                    a = fmaf(xs[c][t + kw], wr[c*3 + kw], a);
            orow[t] = __float2half_rn(a);
            s += a; q += a*a;
        }
#pragma unroll
        for (int d = 16; d; d >>= 1) {
            s += __shfl_xor_sync(0xffffffffu, s, d);
            q += __shfl_xor_sync(0xffffffffu, q, d);
        }
        if (lane == 0) { g_pU[bj*CO + o] = s; g_pUQ[bj*CO + o] = q; }
    }
}

// ---------------- prep: fp16 A fragment images (m16n8k16 layout, per kc32) ----------------
__global__ void k_prep(const float* __restrict__ psw, const float* __restrict__ fusw) {
    int which = blockIdx.x;
    const float* W = which ? fusw : psw;
    int K = which ? K2A : K1A;
    int nslot = which ? 8*512 : 6*512;
    uint4* A = which ? g_Afus : g_Aps;
    for (int s = threadIdx.x; s < nslot; s += blockDim.x) {
        int lane = s & 31, ks = (s >> 5) & 1, g = (s >> 6) & 7, kc = s >> 9;
        int r = g*16 + (lane >> 2);
        int kb = kc*32 + ks*16 + 2*(lane & 3);
        float a00 = (kb   < K) ? W[r*K + kb]       : 0.f;
        float a01 = (kb+1 < K) ? W[r*K + kb+1]     : 0.f;
        float a10 = (kb   < K) ? W[(r+8)*K + kb]   : 0.f;
        float a11 = (kb+1 < K) ? W[(r+8)*K + kb+1] : 0.f;
        float a20 = (kb+8 < K) ? W[r*K + kb+8]     : 0.f;
        float a21 = (kb+9 < K) ? W[r*K + kb+9]     : 0.f;
        float a30 = (kb+8 < K) ? W[(r+8)*K + kb+8] : 0.f;
        float a31 = (kb+9 < K) ? W[(r+8)*K + kb+9] : 0.f;
        A[s] = make_uint4(packh2(a00, a01), packh2(a10, a11),
                          packh2(a20, a21), packh2(a30, a31));
    }
}

// ---------------- fused signature + ps GEMM ----------------
__global__ void __launch_bounds__(256, 2) k_sigps(
        const float* __restrict__ x, const int* __restrict__ path,
        const float* __restrict__ bias) {
    extern __shared__ char smc[];
    __shared__ float sS[CO], sQ[CO];
    uint32_t sb = smem_u32(smc);
    int tid = threadIdx.x;
    int warp = tid >> 5, lane = tid & 31;
    int wm = (warp >> 2) * 64;
    int wn = (warp & 3) * 32;
    int gbase = (warp >> 2) * 4;
    int lq = lane >> 2, lr = lane & 3;
    int p0 = blockIdx.x * NT;

    // prefetch ALL A chunks (48KB) in one group
#pragma unroll
    for (int i = 0; i < 12; i++) {
        int m = tid + i*256;   // 3072 slots
        cp16(sb + PS_A + m*16, g_Aps + m, 16);
    }
    CP_COMMIT();

    if (tid < CO) { sS[tid] = 0.f; sQ[tid] = 0.f; }
    // zero padded B rows 168..191
    for (int i = tid; i < 24*136; i += 256) {
        int row = 168 + i/136, col = i % 136;
        *(__half*)(smc + PS_B + row*272 + col*2) = __float2half_rn(0.f);
    }

    // ---- phase 1: signatures -> B SMEM column pp ----
    {
        int pp = tid & 127;
        int which = tid >> 7;          // 0 = spatial, 1 = temporal
        int p = p0 + pp;
        int t  = p & (TT - 1);
        int bj = p >> 9;
        int j  = bj % JJ;
        int b  = bj / JJ;
        const float* xb = x + (size_t)b * CC * JJ * TT;

        float S1[4], S2[16], S3[64];
        float prev[3], cur[3], d[4];
#pragma unroll
        for (int i = 0; i < 4; i++)  S1[i] = 0.f;
#pragma unroll
        for (int i = 0; i < 16; i++) S2[i] = 0.f;
#pragma unroll
        for (int i = 0; i < 64; i++) S3[i] = 0.f;

        if (which == 0) {
            int j0 = path[j*3+0], j1 = path[j*3+1], j2 = path[j*3+2];
#pragma unroll
            for (int c = 0; c < 3; c++) prev[c] = xb[(c*JJ + j0)*TT + t];
            d[0] = 0.f; d[1] = prev[0]; d[2] = prev[1]; d[3] = prev[2];
            sig_step(S1, S2, S3, d);
#pragma unroll
            for (int c = 0; c < 3; c++) cur[c] = xb[(c*JJ + j1)*TT + t];
            d[0] = 0.5f;
#pragma unroll
            for (int c = 0; c < 3; c++) { d[c+1] = cur[c] - prev[c]; prev[c] = cur[c]; }
            sig_step(S1, S2, S3, d);
#pragma unroll
            for (int c = 0; c < 3; c++) cur[c] = xb[(c*JJ + j2)*TT + t];
            d[0] = 0.5f;
#pragma unroll
            for (int c = 0; c < 3; c++) d[c+1] = cur[c] - prev[c];
            sig_step(S1, S2, S3, d);
        } else {
#pragma unroll
            for (int l = 0; l < 7; l++) {
                int tc = t + l - 3;
                tc = tc < 0 ? 0 : (tc > TT-1 ? TT-1 : tc);
#pragma unroll
                for (int c = 0; c < 3; c++) cur[c] = xb[(c*JJ + j)*TT + tc];
                if (l == 0) {
                    d[0] = 0.f;
#pragma unroll
                    for (int c = 0; c < 3; c++) d[c+1] = cur[c];
                } else {
                    d[0] = 1.0f/6.0f;
#pragma unroll
                    for (int c = 0; c < 3; c++) d[c+1] = cur[c] - prev[c];
                }
#pragma unroll
                for (int c = 0; c < 3; c++) prev[c] = cur[c];
                sig_step(S1, S2, S3, d);
            }
        }
        // write 84 rows at rowbase = which*84, column pp
        char* B = smc + PS_B;
        int rowbase = which * SIGC;
#pragma unroll
        for (int i = 0; i < 4; i++)
            *(__half*)(B + (rowbase + i)*272 + pp*2) = __float2half_rn(S1[i]);
#pragma unroll
        for (int i = 0; i < 16; i++)
            *(__half*)(B + (rowbase + 4 + i)*272 + pp*2) = __float2half_rn(S2[i]);
#pragma unroll
        for (int i = 0; i < 64; i++)
            *(__half*)(B + (rowbase + 20 + i)*272 + pp*2) = __float2half_rn(S3[i]);
    }

    CP_WAIT0();
    __syncthreads();          // B complete + A visible

    // ---- phase 2: MMA, 3 chunks of K=64, no in-loop barriers ----
    float acc[4][4][4];
#pragma unroll
    for (int i = 0; i < 4; i++)
#pragma unroll
        for (int j = 0; j < 4; j++)
#pragma unroll
            for (int r = 0; r < 4; r++) acc[i][j][r] = 0.f;

#pragma unroll 1
    for (int c = 0; c < 3; c++) {
        const char* Ac = smc + PS_A + c*16384;
#pragma unroll
        for (int ks = 0; ks < 4; ks++) {
            const char* Ak = Ac + (ks >> 1)*8192;
            uint4 af[4];
#pragma unroll
            for (int i = 0; i < 4; i++)
                af[i] = *(const uint4*)(Ak + (gbase + i)*1024 + (ks & 1)*512 + lane*16);
#pragma unroll
            for (int j = 0; j < 4; j++) {
                uint32_t b[2];
                uint32_t boff = (uint32_t)((c*64 + ks*16 + (lane & 15))*272 + (wn + j*8)*2);
                ldsm_x2_t(b, sb + PS_B + boff);
#pragma unroll
                for (int i = 0; i < 4; i++)
                    mma_f16(acc[i][j], af[i], b[0], b[1]);
            }
        }
    }

    // ---- epilogue: bias, store V fp16 channel-major, fused BN partials ----
    __half* Out = g_UVh + (size_t)CO*NPTS;
#pragma unroll
    for (int i = 0; i < 4; i++) {
        int c0 = wm + i*16 + lq;
        int c1 = c0 + 8;
        float b0 = bias[c0], b1 = bias[c1];
        float s0 = 0.f, q0 = 0.f, s1 = 0.f, q1 = 0.f;
#pragma unroll
        for (int j = 0; j < 4; j++) {
            float v00 = acc[i][j][0] + b0, v01 = acc[i][j][1] + b0;
            float v10 = acc[i][j][2] + b1, v11 = acc[i][j][3] + b1;
            int p = p0 + wn + j*8 + (lr << 1);
            *(__half2*)&Out[(size_t)c0*NPTS + p] = __floats2half2_rn(v00, v01);
            *(__half2*)&Out[(size_t)c1*NPTS + p] = __floats2half2_rn(v10, v11);
            s0 += v00 + v01; q0 += v00*v00 + v01*v01;
            s1 += v10 + v11; q1 += v10*v10 + v11*v11;
        }
#pragma unroll
        for (int d = 1; d < 4; d <<= 1) {
            s0 += __shfl_xor_sync(0xffffffffu, s0, d);
            q0 += __shfl_xor_sync(0xffffffffu, q0, d);
            s1 += __shfl_xor_sync(0xffffffffu, s1, d);
            q1 += __shfl_xor_sync(0xffffffffu, q1, d);
        }
        if (lr == 0) {
            atomicAdd(&sS[c0], s0); atomicAdd(&sQ[c0], q0);
            atomicAdd(&sS[c1], s1); atomicAdd(&sQ[c1], q1);
        }
    }
    __syncthreads();
    if (tid < CO) {
        g_pV[blockIdx.x*CO + tid]  = sS[tid];
        g_pVQ[blockIdx.x*CO + tid] = sQ[tid];
    }
}

// ---------------- fus GEMM building blocks (KS=64) ----------------
__device__ __forceinline__ void issueAf(int c, int tid, uint32_t sb) {
#pragma unroll
    for (int i = 0; i < 4; i++) {
        int m = tid + i*256;
        cp16(sb + OFF_A(c & 1) + m*16, g_Afus + c*1024 + m, 16);
    }
}
__device__ __forceinline__ void issueRaw(int c, int tid, uint32_t sb, int p0) {
#pragma unroll
    for (int i = 0; i < 4; i++) {
        int m = tid + i*256;
        int kl = m >> 4;
        const __half* src = g_UVh + (size_t)(c*KS + kl)*NPTS + p0 + (m & 15)*8;
        cp16(sb + OFF_RAW(c & 1) + m*16, src, 16);
    }
}
__device__ __forceinline__ void convF(int cc, int tid, char* smc,
        const float* s_sc, const float* s_bi) {
    const char* raw = smc + OFF_RAW(cc & 1);
    char* B = smc + OFF_B(cc & 1);
#pragma unroll
    for (int i = 0; i < 4; i++) {
        int m = tid + i*256;
        int kl = m >> 4, seg = m & 15;
        uint4 v = *(const uint4*)(raw + m*16);
        int kg = cc*KS + kl;
        float sc = s_sc[kg], bi = s_bi[kg];
        uint4 o;
        uint32_t* vp = (uint32_t*)&v;
        uint32_t* op = (uint32_t*)&o;
#pragma unroll
        for (int q = 0; q < 4; q++) {
            float2 f = __half22float2(*(__half2*)&vp[q]);
            f.x = fmaxf(fmaf(f.x, sc, bi), 0.f);
            f.y = fmaxf(fmaf(f.y, sc, bi), 0.f);
            op[q] = packh2(f.x, f.y);
        }
        *(uint4*)(B + kl*272 + seg*16) = o;
    }
}

// ---------------- pipelined fus GEMM ----------------
__global__ void __launch_bounds__(256, 2) k_fus(const float* __restrict__ bias) {
    extern __shared__ char smc[];
    __shared__ float sS[CO], sQ[CO];
    uint32_t sb = smem_u32(smc);
    float* s_sc = (float*)(smc + OFF_SC);
    float* s_bi = (float*)(smc + OFF_BI);

    int tid = threadIdx.x;
    int warp = tid >> 5, lane = tid & 31;
    int wm = (warp >> 2) * 64;
    int wn = (warp & 3) * 32;
    int gbase = (warp >> 2) * 4;
    int lq = lane >> 2, lr = lane & 3;
    int p0 = blockIdx.x * NT;

    for (int i = tid; i < K2A; i += 256) { s_sc[i] = g_sc1[i]; s_bi[i] = g_bi1[i]; }
    if (tid < CO) { sS[tid] = 0.f; sQ[tid] = 0.f; }
    __syncthreads();

    float acc[4][4][4];
#pragma unroll
    for (int i = 0; i < 4; i++)
#pragma unroll
        for (int j = 0; j < 4; j++)
#pragma unroll
            for (int r = 0; r < 4; r++) acc[i][j][r] = 0.f;

    issueAf(0, tid, sb); issueRaw(0, tid, sb, p0); CP_COMMIT();
    issueAf(1, tid, sb); issueRaw(1, tid, sb, p0); CP_COMMIT();
    CP_WAIT1();
    convF(0, tid, smc, s_sc, s_bi);
    __syncthreads();

    for (int c = 0; c < 4; c++) {
        int s = c & 1;
        const char* As = smc + OFF_A(s);
#pragma unroll
        for (int ks = 0; ks < 4; ks++) {
            const char* Ak = As + (ks >> 1)*8192;
            uint4 af[4];
#pragma unroll
            for (int i = 0; i < 4; i++)
                af[i] = *(const uint4*)(Ak + (gbase + i)*1024 + (ks & 1)*512 + lane*16);
#pragma unroll
            for (int j = 0; j < 4; j++) {
                uint32_t b[2];
                uint32_t boff = (uint32_t)((ks*16 + (lane & 15))*272 + (wn + j*8)*2);
                ldsm_x2_t(b, sb + OFF_B(s) + boff);
#pragma unroll
                for (int i = 0; i < 4; i++)
                    mma_f16(acc[i][j], af[i], b[0], b[1]);
            }
        }
        __syncthreads();
        if (c + 2 < 4) { issueAf(c+2, tid, sb); issueRaw(c+2, tid, sb, p0); }
        CP_COMMIT();
        CP_WAIT1();
        if (c + 1 < 4) convF(c+1, tid, smc, s_sc, s_bi);
        __syncthreads();
    }

    // ---- epilogue ----
#pragma unroll
    for (int i = 0; i < 4; i++) {
        int c0 = wm + i*16 + lq;
        int c1 = c0 + 8;
        float b0 = bias[c0], b1 = bias[c1];
        float s0 = 0.f, q0 = 0.f, s1 = 0.f, q1 = 0.f;
#pragma unroll
        for (int j = 0; j < 4; j++) {
            float v00 = acc[i][j][0] + b0, v01 = acc[i][j][1] + b0;
            float v10 = acc[i][j][2] + b1, v11 = acc[i][j][3] + b1;
            int p = p0 + wn + j*8 + (lr << 1);
            *(__half2*)&g_Fh[(size_t)c0*NPTS + p] = __floats2half2_rn(v00, v01);
            *(__half2*)&g_Fh[(size_t)c1*NPTS + p] = __floats2half2_rn(v10, v11);
            s0 += v00 + v01; q0 += v00*v00 + v01*v01;
            s1 += v10 + v11; q1 += v10*v10 + v11*v11;
        }
#pragma unroll
        for (int d = 1; d < 4; d <<= 1) {
            s0 += __shfl_xor_sync(0xffffffffu, s0, d);
            q0 += __shfl_xor_sync(0xffffffffu, q0, d);
            s1 += __shfl_xor_sync(0xffffffffu, s1, d);
            q1 += __shfl_xor_sync(0xffffffffu, q1, d);
        }
        if (lr == 0) {
            atomicAdd(&sS[c0], s0); atomicAdd(&sQ[c0], q0);
            atomicAdd(&sS[c1], s1); atomicAdd(&sQ[c1], q1);
        }
    }
    __syncthreads();
    if (tid < CO) {
        g_pF[blockIdx.x*CO + tid]  = sS[tid];
        g_pFQ[blockIdx.x*CO + tid] = sQ[tid];
    }
}

// ---------------- finalize BN affines ----------------
__global__ void k_fin1(const float* __restrict__ rg, const float* __restrict__ rb,
                       const float* __restrict__ pg, const float* __restrict__ pb) {
    int c = blockIdx.x;   // 0..255
    float s = 0.f, q = 0.f;
    if (c < CO) {
        for (int i = threadIdx.x; i < RAWG; i += 128) { s += g_pU[i*CO + c]; q += g_pUQ[i*CO + c]; }
    } else {
        int cc = c - CO;
        for (int i = threadIdx.x; i < GRIDG; i += 128) { s += g_pV[i*CO + cc]; q += g_pVQ[i*CO + cc]; }
    }
    __shared__ float sh[256];
    sh[threadIdx.x] = s; sh[128 + threadIdx.x] = q;
    __syncthreads();
    for (int st = 64; st; st >>= 1) {
        if (threadIdx.x < st) {
            sh[threadIdx.x]       += sh[threadIdx.x + st];
            sh[128 + threadIdx.x] += sh[128 + threadIdx.x + st];
        }
        __syncthreads();
    }
    if (threadIdx.x == 0) {
        float mean = sh[0] / (float)NPTS;
        float var  = sh[128] / (float)NPTS - mean*mean;
        float rstd = rsqrtf(var + 1e-5f);
        float g  = (c < CO) ? rg[c] : pg[c - CO];
        float be = (c < CO) ? rb[c] : pb[c - CO];
        g_sc1[c] = rstd * g;
        g_bi1[c] = be - mean * rstd * g;
    }
}

__global__ void k_fin2(const float* __restrict__ fg, const float* __restrict__ fb) {
    int c = blockIdx.x;   // 0..127
    float s = 0.f, q = 0.f;
    for (int i = threadIdx.x; i < GRIDG; i += 128) { s += g_pF[i*CO + c]; q += g_pFQ[i*CO + c]; }
    __shared__ float sh[256];
    sh[threadIdx.x] = s; sh[128 + threadIdx.x] = q;
    __syncthreads();
    for (int st = 64; st; st >>= 1) {
        if (threadIdx.x < st) {
            sh[threadIdx.x]       += sh[threadIdx.x + st];
            sh[128 + threadIdx.x] += sh[128 + threadIdx.x + st];
        }
        __syncthreads();
    }
    if (threadIdx.x == 0) {
        float mean = sh[0] / (float)NPTS;
        float var  = sh[128] / (float)NPTS - mean*mean;
        float rstd = rsqrtf(var + 1e-5f);
        g_sc2[c] = rstd * fg[c];
        g_bi2[c] = fb[c] - mean * rstd * fg[c];
    }
}

// ---------------- final affine + relu + reshape (8 fp16 per thread) ----------------
__global__ void k_out(float* __restrict__ out) {
    int e8 = blockIdx.x * 256 + threadIdx.x;
    int idx = e8 << 3;
    int o = idx / NPTS;
    int p = idx - o * NPTS;
    int t  = p & (TT - 1);
    int bj = p >> 9;
    int j  = bj % JJ;
    int b  = bj / JJ;
    uint4 v = *(const uint4*)&g_Fh[idx];
    float sc = g_sc2[o], bi = g_bi2[o];
    const uint32_t* vp = (const uint32_t*)&v;
    float r[8];
#pragma unroll
    for (int q = 0; q < 4; q++) {
        float2 f = __half22float2(*(const __half2*)&vp[q]);
        r[q*2+0] = fmaxf(fmaf(f.x, sc, bi), 0.f);
        r[q*2+1] = fmaxf(fmaf(f.y, sc, bi), 0.f);
    }
    float* dst = &out[((b*CO + o)*JJ + j)*TT + t];
    *(float4*)dst       = make_float4(r[0], r[1], r[2], r[3]);
    *(float4*)(dst + 4) = make_float4(r[4], r[5], r[6], r[7]);
}

// ---------------- launcher ----------------
extern "C" void kernel_launch(void* const* d_in, const int* in_sizes, int n_in,
                              void* d_out, int out_size) {
    const float* x      = (const float*)d_in[0];
    const int*   path   = (const int*)  d_in[1];
    const float* raw_w  = (const float*)d_in[2];
    const float* raw_b  = (const float*)d_in[3];
    const float* raw_g  = (const float*)d_in[4];
    const float* raw_be = (const float*)d_in[5];
    const float* ps_w   = (const float*)d_in[6];
    const float* ps_b   = (const float*)d_in[7];
    const float* ps_g   = (const float*)d_in[8];
    const float* ps_be  = (const float*)d_in[9];
    const float* fus_w  = (const float*)d_in[10];
    const float* fus_b  = (const float*)d_in[11];
    const float* fus_g  = (const float*)d_in[12];
    const float* fus_be = (const float*)d_in[13];
    float* out = (float*)d_out;

    cudaFuncSetAttribute(k_sigps, cudaFuncAttributeMaxDynamicSharedMemorySize, SMEM_PS);
    cudaFuncSetAttribute(k_fus,   cudaFuncAttributeMaxDynamicSharedMemorySize, SMEM_FUS);

    k_prep<<<2, 256>>>(ps_w, fus_w);
    k_raw<<<RAWG, 256>>>(x, raw_w, raw_b);
    k_sigps<<<GRIDG, 256, SMEM_PS>>>(x, path, ps_b);
    k_fin1<<<2*CO, 128>>>(raw_g, raw_be, ps_g, ps_be);
    k_fus<<<GRIDG, 256, SMEM_FUS>>>(fus_b);
    k_fin2<<<CO, 128>>>(fus_g, fus_be);
    k_out<<<(CO*NPTS)/2048, 256>>>(out);
}